// round 4
// baseline (speedup 1.0000x reference)
#include <cuda_runtime.h>
#include <math.h>

// ---------------------------------------------------------------------------
// Shapes (compile-time, from the reference)
// ---------------------------------------------------------------------------
#define B_SZ   2
#define SEQ    2048
#define MROWS  4096          // B_SZ * SEQ
#define DM     1024          // d_model
#define DI     2048          // d_inner
#define CONVD  2176          // conv dim = d_inner + 2*d_state
#define DIP    4256          // in_proj out dim = 2*DI + 2*64 + 32
#define NH     32            // heads
#define HD     64            // head dim
#define DS     64            // state dim
#define FFN    4096

// ---------------------------------------------------------------------------
// Scratch buffers: static __device__ globals (no allocation allowed)
// ---------------------------------------------------------------------------
__device__ __align__(256) float g_x0 [MROWS * DM];    // after LN0 (residual stream)
__device__ __align__(256) float g_u  [MROWS * DM];    // after LN1 (mamba input)
__device__ __align__(256) float g_zx [MROWS * DIP];   // in_proj output
__device__ __align__(256) float g_xc [MROWS * CONVD]; // conv+silu output
__device__ __align__(256) float g_dt [MROWS * NH];
__device__ __align__(256) float g_dA [MROWS * NH];
__device__ __align__(256) float g_ydp[MROWS * DI];    // scan output + D*x
__device__ __align__(256) float g_yn [MROWS * DI];    // after gate + rmsnorm
__device__ __align__(256) float g_x1 [MROWS * DM];    // x0 + out_proj(yn)
__device__ __align__(256) float g_hln[MROWS * DM];    // LN2(x1)
__device__ __align__(256) float g_t  [MROWS * FFN];   // gelu(ffn1)

// ---------------------------------------------------------------------------
// Block reduce (blockDim.x == 256) of two values
// ---------------------------------------------------------------------------
__device__ __forceinline__ float2 block_reduce2(float a, float b) {
    __shared__ float sa[8], sb[8];
    int lane = threadIdx.x & 31, w = threadIdx.x >> 5;
#pragma unroll
    for (int o = 16; o; o >>= 1) {
        a += __shfl_xor_sync(0xffffffffu, a, o);
        b += __shfl_xor_sync(0xffffffffu, b, o);
    }
    __syncthreads();               // protect smem reuse across calls
    if (lane == 0) { sa[w] = a; sb[w] = b; }
    __syncthreads();
    float ta = 0.f, tb = 0.f;
#pragma unroll
    for (int i = 0; i < 8; i++) { ta += sa[i]; tb += sb[i]; }
    return make_float2(ta, tb);
}

// ---------------------------------------------------------------------------
// Fused LN0 -> LN1 (one block per row of 1024, 256 threads, 4 elems/thread)
// writes g_x0 (post-LN0) and g_u (post-LN1)
// ---------------------------------------------------------------------------
__global__ void ln01_kernel(const float* __restrict__ x,
                            const float* __restrict__ w0, const float* __restrict__ b0,
                            const float* __restrict__ w1, const float* __restrict__ b1) {
    int row = blockIdx.x;
    int t = threadIdx.x;
    const float* xr = x + (size_t)row * DM;
    float4 v = *(const float4*)(xr + t * 4);

    float s  = v.x + v.y + v.z + v.w;
    float ss = v.x*v.x + v.y*v.y + v.z*v.z + v.w*v.w;
    float2 r0 = block_reduce2(s, ss);
    float mean = r0.x * (1.f / DM);
    float var  = r0.y * (1.f / DM) - mean * mean;
    float rs = rsqrtf(var + 1e-5f);

    int c = t * 4;
    float y0 = (v.x - mean) * rs * w0[c + 0] + b0[c + 0];
    float y1 = (v.y - mean) * rs * w0[c + 1] + b0[c + 1];
    float y2 = (v.z - mean) * rs * w0[c + 2] + b0[c + 2];
    float y3 = (v.w - mean) * rs * w0[c + 3] + b0[c + 3];
    *(float4*)(g_x0 + (size_t)row * DM + c) = make_float4(y0, y1, y2, y3);

    s  = y0 + y1 + y2 + y3;
    ss = y0*y0 + y1*y1 + y2*y2 + y3*y3;
    float2 r1 = block_reduce2(s, ss);
    mean = r1.x * (1.f / DM);
    var  = r1.y * (1.f / DM) - mean * mean;
    rs = rsqrtf(var + 1e-5f);

    float u0 = (y0 - mean) * rs * w1[c + 0] + b1[c + 0];
    float u1 = (y1 - mean) * rs * w1[c + 1] + b1[c + 1];
    float u2 = (y2 - mean) * rs * w1[c + 2] + b1[c + 2];
    float u3 = (y3 - mean) * rs * w1[c + 3] + b1[c + 3];
    *(float4*)(g_u + (size_t)row * DM + c) = make_float4(u0, u1, u2, u3);
}

// ---------------------------------------------------------------------------
// LN2: g_hln = LN(g_x1)
// ---------------------------------------------------------------------------
__global__ void ln2_kernel(const float* __restrict__ w, const float* __restrict__ b) {
    int row = blockIdx.x;
    int t = threadIdx.x;
    float4 v = *(const float4*)(g_x1 + (size_t)row * DM + t * 4);
    float s  = v.x + v.y + v.z + v.w;
    float ss = v.x*v.x + v.y*v.y + v.z*v.z + v.w*v.w;
    float2 r0 = block_reduce2(s, ss);
    float mean = r0.x * (1.f / DM);
    float var  = r0.y * (1.f / DM) - mean * mean;
    float rs = rsqrtf(var + 1e-5f);
    int c = t * 4;
    float4 o;
    o.x = (v.x - mean) * rs * w[c + 0] + b[c + 0];
    o.y = (v.y - mean) * rs * w[c + 1] + b[c + 1];
    o.z = (v.z - mean) * rs * w[c + 2] + b[c + 2];
    o.w = (v.w - mean) * rs * w[c + 3] + b[c + 3];
    *(float4*)(g_hln + (size_t)row * DM + c) = o;
}

// ---------------------------------------------------------------------------
// SGEMM: C[M,N] = A[M,K] * B[N,K]^T  (+ epilogue)
// EPI: 0 = store, 1 = bias + exact gelu, 2 = bias + residual, 3 = residual
// 128x128 tile, BK=16, 256 threads, 8x8 microtile
// M must be a multiple of 128 and K a multiple of 16 (true here); N arbitrary.
// ---------------------------------------------------------------------------
template<int EPI>
__global__ __launch_bounds__(256, 2)
void sgemm_kernel(const float* __restrict__ A, const float* __restrict__ Bm,
                  float* __restrict__ C, const float* __restrict__ bias,
                  const float* __restrict__ R, int M, int N, int K) {
    __shared__ float As[16][132];
    __shared__ float Bs[16][132];
    int tid = threadIdx.x;
    int row0 = blockIdx.y * 128, col0 = blockIdx.x * 128;

    int lr = tid >> 2;            // 0..63
    int lc = (tid & 3) << 2;      // 0,4,8,12
    int ar = (tid >> 4) << 3;     // 0..120 step 8
    int bc = (tid & 15) << 3;     // 0..120 step 8

    const float* Ap0 = A + (size_t)(row0 + lr) * K + lc;
    const float* Ap1 = Ap0 + (size_t)64 * K;
    int n1 = col0 + lr, n2 = n1 + 64;
    const float* Bp0 = Bm + (size_t)n1 * K + lc;
    const float* Bp1 = Bm + (size_t)n2 * K + lc;
    bool bok1 = n1 < N, bok2 = n2 < N;

    float acc[8][8];
#pragma unroll
    for (int i = 0; i < 8; i++)
#pragma unroll
        for (int j = 0; j < 8; j++) acc[i][j] = 0.f;

    for (int k0 = 0; k0 < K; k0 += 16) {
        float4 a0 = *(const float4*)(Ap0 + k0);
        float4 a1 = *(const float4*)(Ap1 + k0);
        float4 b0 = bok1 ? *(const float4*)(Bp0 + k0) : make_float4(0.f, 0.f, 0.f, 0.f);
        float4 b1 = bok2 ? *(const float4*)(Bp1 + k0) : make_float4(0.f, 0.f, 0.f, 0.f);

        __syncthreads();
        As[lc + 0][lr] = a0.x; As[lc + 1][lr] = a0.y; As[lc + 2][lr] = a0.z; As[lc + 3][lr] = a0.w;
        As[lc + 0][lr + 64] = a1.x; As[lc + 1][lr + 64] = a1.y; As[lc + 2][lr + 64] = a1.z; As[lc + 3][lr + 64] = a1.w;
        Bs[lc + 0][lr] = b0.x; Bs[lc + 1][lr] = b0.y; Bs[lc + 2][lr] = b0.z; Bs[lc + 3][lr] = b0.w;
        Bs[lc + 0][lr + 64] = b1.x; Bs[lc + 1][lr + 64] = b1.y; Bs[lc + 2][lr + 64] = b1.z; Bs[lc + 3][lr + 64] = b1.w;
        __syncthreads();

#pragma unroll
        for (int kk = 0; kk < 16; kk++) {
            float4 av0 = *(const float4*)&As[kk][ar];
            float4 av1 = *(const float4*)&As[kk][ar + 4];
            float4 bv0 = *(const float4*)&Bs[kk][bc];
            float4 bv1 = *(const float4*)&Bs[kk][bc + 4];
            float a[8] = {av0.x, av0.y, av0.z, av0.w, av1.x, av1.y, av1.z, av1.w};
            float b[8] = {bv0.x, bv0.y, bv0.z, bv0.w, bv1.x, bv1.y, bv1.z, bv1.w};
#pragma unroll
            for (int i = 0; i < 8; i++)
#pragma unroll
                for (int j = 0; j < 8; j++)
                    acc[i][j] = fmaf(a[i], b[j], acc[i][j]);
        }
    }

#pragma unroll
    for (int i = 0; i < 8; i++) {
        int r = row0 + ar + i;
#pragma unroll
        for (int j = 0; j < 8; j++) {
            int c = col0 + bc + j;
            if (c < N) {
                float v = acc[i][j];
                if (EPI == 1) {
                    v += bias[c];
                    v = 0.5f * v * (1.f + erff(v * 0.70710678118654752f));
                } else if (EPI == 2) {
                    v += bias[c] + R[(size_t)r * N + c];
                } else if (EPI == 3) {
                    v += R[(size_t)r * N + c];
                }
                C[(size_t)r * N + c] = v;
            }
        }
    }
}

// ---------------------------------------------------------------------------
// Causal depthwise conv (k=4) + silu over xBC columns of g_zx
// ---------------------------------------------------------------------------
__global__ void conv_silu_kernel(const float* __restrict__ cw, const float* __restrict__ cb) {
    int c = blockIdx.x * blockDim.x + threadIdx.x;
    if (c >= CONVD) return;
    int r = blockIdx.y;                    // 0..MROWS-1
    int b = r >> 11, l = r & (SEQ - 1);
    float w0 = cw[c * 4 + 0], w1 = cw[c * 4 + 1], w2 = cw[c * 4 + 2], w3 = cw[c * 4 + 3];
    const float* base = g_zx + (size_t)(b * SEQ) * DIP + DI + c;
    float acc = cb[c];
    if (l >= 3) acc = fmaf(w0, base[(size_t)(l - 3) * DIP], acc);
    if (l >= 2) acc = fmaf(w1, base[(size_t)(l - 2) * DIP], acc);
    if (l >= 1) acc = fmaf(w2, base[(size_t)(l - 1) * DIP], acc);
    acc = fmaf(w3, base[(size_t)l * DIP], acc);
    float sig = 1.f / (1.f + expf(-acc));
    g_xc[(size_t)r * CONVD + c] = acc * sig;
}

// ---------------------------------------------------------------------------
// dt = softplus(raw + dt_bias), dA = exp(-exp(A_log)*dt)
// ---------------------------------------------------------------------------
__global__ void dt_kernel(const float* __restrict__ dt_bias, const float* __restrict__ A_log) {
    int i = blockIdx.x * blockDim.x + threadIdx.x;   // < MROWS*NH
    int r = i >> 5, hh = i & 31;
    float raw = g_zx[(size_t)r * DIP + (DI + CONVD) + hh];
    float v = raw + dt_bias[hh];
    float sp = (v > 20.f) ? v : log1pf(expf(v));
    g_dt[i] = sp;
    g_dA[i] = expf(-expf(A_log[hh]) * sp);
}

// ---------------------------------------------------------------------------
// Selective scan: one CTA per (b, h); 512 threads; state in registers.
// thread -> p = tid/8, owns n0 = (tid%8)*8 .. +8 of the 64-state dim.
// ---------------------------------------------------------------------------
__global__ __launch_bounds__(512, 1)
void scan_kernel(const float* __restrict__ Dp) {
    int bh = blockIdx.x;
    int b = bh >> 5, h = bh & 31;
    int tid = threadIdx.x;
    int p = tid >> 3, sub = tid & 7, n0 = sub << 3;

    __shared__ __align__(16) float sx[2][64];
    __shared__ __align__(16) float sB[2][64];
    __shared__ __align__(16) float sC[2][64];
    __shared__ float sdt[2][2];

    float hs[8];
#pragma unroll
    for (int i = 0; i < 8; i++) hs[i] = 0.f;
    float Dv = Dp[h];

    const float* xcb = g_xc + (size_t)(b * SEQ) * CONVD;
    float* yb = g_ydp + (size_t)(b * SEQ) * DI;

    for (int l = 0; l < SEQ; l++) {
        int buf = l & 1;
        const float* xr = xcb + (size_t)l * CONVD;
        if (tid < 64)        sx[buf][tid]       = xr[h * 64 + tid];
        else if (tid < 128)  sB[buf][tid - 64]  = xr[2048 + (tid - 64)];
        else if (tid < 192)  sC[buf][tid - 128] = xr[2112 + (tid - 128)];
        else if (tid == 192) {
            int ri = (b * SEQ + l) * NH + h;
            sdt[buf][0] = g_dt[ri];
            sdt[buf][1] = g_dA[ri];
        }
        __syncthreads();

        float dtv = sdt[buf][0], dAv = sdt[buf][1];
        float xv = sx[buf][p];
        float dtx = dtv * xv;
        float4 Bv0 = *(const float4*)&sB[buf][n0];
        float4 Bv1 = *(const float4*)&sB[buf][n0 + 4];
        float4 Cv0 = *(const float4*)&sC[buf][n0];
        float4 Cv1 = *(const float4*)&sC[buf][n0 + 4];

        float part;
        hs[0] = fmaf(hs[0], dAv, dtx * Bv0.x); part  = hs[0] * Cv0.x;
        hs[1] = fmaf(hs[1], dAv, dtx * Bv0.y); part += hs[1] * Cv0.y;
        hs[2] = fmaf(hs[2], dAv, dtx * Bv0.z); part += hs[2] * Cv0.z;
        hs[3] = fmaf(hs[3], dAv, dtx * Bv0.w); part += hs[3] * Cv0.w;
        hs[4] = fmaf(hs[4], dAv, dtx * Bv1.x); part += hs[4] * Cv1.x;
        hs[5] = fmaf(hs[5], dAv, dtx * Bv1.y); part += hs[5] * Cv1.y;
        hs[6] = fmaf(hs[6], dAv, dtx * Bv1.z); part += hs[6] * Cv1.z;
        hs[7] = fmaf(hs[7], dAv, dtx * Bv1.w); part += hs[7] * Cv1.w;

        part += __shfl_xor_sync(0xffffffffu, part, 1);
        part += __shfl_xor_sync(0xffffffffu, part, 2);
        part += __shfl_xor_sync(0xffffffffu, part, 4);

        if (sub == 0)
            yb[(size_t)l * DI + h * 64 + p] = fmaf(Dv, xv, part);
        // one barrier per step is enough: double-buffered smem
    }
}

// ---------------------------------------------------------------------------
// Gate (y * silu(z)) + RMSNorm with norm_w -> g_yn
// ---------------------------------------------------------------------------
__global__ void gate_rms_kernel(const float* __restrict__ norm_w) {
    int row = blockIdx.x;
    int t = threadIdx.x;
    const float* zr = g_zx + (size_t)row * DIP;         // z = first 2048 cols
    const float* yr = g_ydp + (size_t)row * DI;
    int c0 = t * 8;

    float g[8];
    float ss = 0.f;
#pragma unroll
    for (int k = 0; k < 2; k++) {
        float4 zv = *(const float4*)(zr + c0 + k * 4);
        float4 yv = *(const float4*)(yr + c0 + k * 4);
        float z0 = zv.x, z1 = zv.y, z2 = zv.z, z3 = zv.w;
        float g0 = yv.x * (z0 / (1.f + expf(-z0)));
        float g1 = yv.y * (z1 / (1.f + expf(-z1)));
        float g2 = yv.z * (z2 / (1.f + expf(-z2)));
        float g3 = yv.w * (z3 / (1.f + expf(-z3)));
        g[k * 4 + 0] = g0; g[k * 4 + 1] = g1; g[k * 4 + 2] = g2; g[k * 4 + 3] = g3;
        ss += g0 * g0 + g1 * g1 + g2 * g2 + g3 * g3;
    }
    float2 r = block_reduce2(ss, 0.f);
    float rs = rsqrtf(r.x * (1.f / DI) + 1e-5f);

    float* outr = g_yn + (size_t)row * DI;
#pragma unroll
    for (int k = 0; k < 2; k++) {
        float4 o;
        o.x = g[k * 4 + 0] * rs * norm_w[c0 + k * 4 + 0];
        o.y = g[k * 4 + 1] * rs * norm_w[c0 + k * 4 + 1];
        o.z = g[k * 4 + 2] * rs * norm_w[c0 + k * 4 + 2];
        o.w = g[k * 4 + 3] * rs * norm_w[c0 + k * 4 + 3];
        *(float4*)(outr + c0 + k * 4) = o;
    }
}

// ---------------------------------------------------------------------------
// Host launcher
// ---------------------------------------------------------------------------
extern "C" void kernel_launch(void* const* d_in, const int* in_sizes, int n_in,
                              void* d_out, int out_size) {
    const float* x         = (const float*)d_in[0];
    const float* ln0_w     = (const float*)d_in[1];
    const float* ln0_b     = (const float*)d_in[2];
    const float* ln1_w     = (const float*)d_in[3];
    const float* ln1_b     = (const float*)d_in[4];
    const float* ln2_w     = (const float*)d_in[5];
    const float* ln2_b     = (const float*)d_in[6];
    const float* in_proj_w = (const float*)d_in[7];
    const float* conv_w    = (const float*)d_in[8];
    const float* conv_b    = (const float*)d_in[9];
    const float* dt_bias   = (const float*)d_in[10];
    const float* A_log     = (const float*)d_in[11];
    const float* D_param   = (const float*)d_in[12];
    const float* norm_w    = (const float*)d_in[13];
    const float* out_proj_w= (const float*)d_in[14];
    const float* ffn_w1    = (const float*)d_in[15];
    const float* ffn_b1    = (const float*)d_in[16];
    const float* ffn_w2    = (const float*)d_in[17];
    const float* ffn_b2    = (const float*)d_in[18];
    float* out = (float*)d_out;

    float *pu, *px0, *pzx, *pyn, *px1, *phln, *pt;
    cudaGetSymbolAddress((void**)&pu,   g_u);
    cudaGetSymbolAddress((void**)&px0,  g_x0);
    cudaGetSymbolAddress((void**)&pzx,  g_zx);
    cudaGetSymbolAddress((void**)&pyn,  g_yn);
    cudaGetSymbolAddress((void**)&px1,  g_x1);
    cudaGetSymbolAddress((void**)&phln, g_hln);
    cudaGetSymbolAddress((void**)&pt,   g_t);

    // 1. LN0 + LN1
    ln01_kernel<<<MROWS, 256>>>(x, ln0_w, ln0_b, ln1_w, ln1_b);

    // 2. in_proj GEMM: [4096,1024] x [4256,1024]^T -> [4096,4256]
    sgemm_kernel<0><<<dim3((DIP + 127) / 128, MROWS / 128), 256>>>(
        pu, in_proj_w, pzx, nullptr, nullptr, MROWS, DIP, DM);

    // 3. causal conv + silu
    conv_silu_kernel<<<dim3((CONVD + 255) / 256, MROWS), 256>>>(conv_w, conv_b);

    // 4. dt / dA
    dt_kernel<<<(MROWS * NH) / 256, 256>>>(dt_bias, A_log);

    // 5. selective scan
    scan_kernel<<<B_SZ * NH, 512>>>(D_param);

    // 6. gate + rmsnorm
    gate_rms_kernel<<<MROWS, 256>>>(norm_w);

    // 7. out_proj GEMM + residual(x0) -> x1
    sgemm_kernel<3><<<dim3(DM / 128, MROWS / 128), 256>>>(
        pyn, out_proj_w, px1, nullptr, px0, MROWS, DM, DI);

    // 8. LN2
    ln2_kernel<<<MROWS, 256>>>(ln2_w, ln2_b);

    // 9. FFN1 GEMM + bias + gelu
    sgemm_kernel<1><<<dim3(FFN / 128, MROWS / 128), 256>>>(
        phln, ffn_w1, pt, ffn_b1, nullptr, MROWS, FFN, DM);

    // 10. FFN2 GEMM + bias + residual(x1) -> out
    sgemm_kernel<2><<<dim3(DM / 128, MROWS / 128), 256>>>(
        pt, ffn_w2, out, ffn_b2, px1, MROWS, DM, FFN);
}

// round 10
// speedup vs baseline: 1.4078x; 1.4078x over previous
#include <cuda_runtime.h>
#include <cuda_bf16.h>
#include <math.h>
#include <stdint.h>

// ---------------------------------------------------------------------------
// Shapes
// ---------------------------------------------------------------------------
#define B_SZ   2
#define SEQ    2048
#define MROWS  4096
#define DM     1024
#define DI     2048
#define CONVD  2176
#define DIP    4256
#define NH     32
#define FFN    4096

// GEMM tiling (mma.sync path)
#define BM     128
#define BN     128
#define BKE    32          // bf16 elems per K iteration
#define ROWB   80          // smem bytes per row (64B data + 16B skew -> conflict-free ldmatrix)
#define ATILE  (128 * ROWB)

// ---------------------------------------------------------------------------
// Scratch (static device globals; no allocation allowed)
// ---------------------------------------------------------------------------
__device__ __align__(256) float g_x0 [MROWS * DM];
__device__ __align__(256) float g_u  [MROWS * DM];
__device__ __align__(256) float g_zx [MROWS * DIP];
__device__ __align__(256) float g_xc [MROWS * CONVD];
__device__ __align__(256) float g_dt [MROWS * NH];
__device__ __align__(256) float g_dA [MROWS * NH];
__device__ __align__(256) float g_ydp[MROWS * DI];
__device__ __align__(256) float g_yn [MROWS * DI];
__device__ __align__(256) float g_x1 [MROWS * DM];
__device__ __align__(256) float g_hln[MROWS * DM];
__device__ __align__(256) float g_t  [MROWS * FFN];
// split-bf16 staging: activations (max 4096 x 12288) and weights (max 4352 x 3072 / 1024 x 12288)
__device__ __align__(256) __nv_bfloat16 g_a2[(size_t)MROWS * 12288];
__device__ __align__(256) __nv_bfloat16 g_b2[(size_t)4352 * 3072];

// ---------------------------------------------------------------------------
// Helpers
// ---------------------------------------------------------------------------
__device__ __forceinline__ uint32_t s2u(const void* p) {
    uint32_t r;
    asm("{ .reg .u64 t; cvta.to.shared.u64 t, %1; cvt.u32.u64 %0, t; }" : "=r"(r) : "l"(p));
    return r;
}
__device__ __forceinline__ void cpa16(uint32_t dst, const void* src) {
    asm volatile("cp.async.cg.shared.global [%0], [%1], 16;" :: "r"(dst), "l"(src));
}
__device__ __forceinline__ void ldsm4(uint32_t* r, uint32_t a) {
    asm volatile("ldmatrix.sync.aligned.m8n8.x4.shared.b16 {%0,%1,%2,%3}, [%4];"
                 : "=r"(r[0]), "=r"(r[1]), "=r"(r[2]), "=r"(r[3]) : "r"(a));
}
__device__ __forceinline__ void mma16816(float* d, const uint32_t* a, const uint32_t* b) {
    asm volatile("mma.sync.aligned.m16n8k16.row.col.f32.bf16.bf16.f32 "
                 "{%0,%1,%2,%3}, {%4,%5,%6,%7}, {%8,%9}, {%0,%1,%2,%3};"
                 : "+f"(d[0]), "+f"(d[1]), "+f"(d[2]), "+f"(d[3])
                 : "r"(a[0]), "r"(a[1]), "r"(a[2]), "r"(a[3]), "r"(b[0]), "r"(b[1]));
}

// ---------------------------------------------------------------------------
// split-bf16 conversion kernels
// act: [hi | lo | hi] along K' = 3K     wt: [hi | hi | lo], rows >= Nreal zeroed
// ---------------------------------------------------------------------------
__global__ void cvt_act(const float* __restrict__ src, __nv_bfloat16* __restrict__ dst, int K) {
    int idx = blockIdx.x * blockDim.x + threadIdx.x;
    int row = idx / K, k = idx - row * K;
    float v = src[idx];
    __nv_bfloat16 hi = __float2bfloat16(v);
    __nv_bfloat16 lo = __float2bfloat16(v - __bfloat162float(hi));
    size_t b = (size_t)row * 3 * K;
    dst[b + k] = hi; dst[b + K + k] = lo; dst[b + 2 * K + k] = hi;
}
__global__ void cvt_wt(const float* __restrict__ src, __nv_bfloat16* __restrict__ dst,
                       int Nreal, int K) {
    int idx = blockIdx.x * blockDim.x + threadIdx.x;
    int row = idx / K, k = idx - row * K;
    float v = (row < Nreal) ? src[(size_t)row * K + k] : 0.f;
    __nv_bfloat16 hi = __float2bfloat16(v);
    __nv_bfloat16 lo = __float2bfloat16(v - __bfloat162float(hi));
    size_t b = (size_t)row * 3 * K;
    dst[b + k] = hi; dst[b + K + k] = hi; dst[b + 2 * K + k] = lo;
}

// ---------------------------------------------------------------------------
// bf16 mma.sync GEMM: C[M,N] = A2[M,Kp] * B2[Npad,Kp]^T, fp32 accumulate
// EPI: 0 none, 1 bias+gelu, 2 bias+residual, 3 residual
// 128x128x32 tile, 256 threads (8 warps, 4x2), warp tile 32x64, m16n8k16
// ---------------------------------------------------------------------------
template<int EPI>
__global__ __launch_bounds__(256, 2)
void gemm_mma(const __nv_bfloat16* __restrict__ A2, const __nv_bfloat16* __restrict__ B2,
              float* __restrict__ C, const float* __restrict__ bias,
              const float* __restrict__ R, int N, int Kp) {
    __shared__ __align__(16) char smA[2][ATILE];
    __shared__ __align__(16) char smB[2][ATILE];

    int tid = threadIdx.x, lane = tid & 31, wid = tid >> 5;
    int row0 = blockIdx.y * BM, col0 = blockIdx.x * BN;
    int wm = (wid & 3) * 32, wn = (wid >> 2) * 64;

    // cp.async chunk assignment: 512 x 16B per tile; thread handles chunks 2t, 2t+1
    int crow = tid >> 1;                  // smem row 0..127
    int cc0  = (tid & 1) * 2;             // chunk 0,1 or 2,3
    size_t KpB = (size_t)Kp * 2;          // row stride bytes in gmem
    const char* gA = (const char*)A2 + (size_t)(row0 + crow) * KpB + cc0 * 16;
    const char* gB = (const char*)B2 + (size_t)(col0 + crow) * KpB + cc0 * 16;
    uint32_t sAW = s2u(smA[0]) + crow * ROWB + cc0 * 16;
    uint32_t sBW = s2u(smB[0]) + crow * ROWB + cc0 * 16;

    float acc[2][8][4];
#pragma unroll
    for (int i = 0; i < 2; i++)
#pragma unroll
        for (int j = 0; j < 8; j++)
#pragma unroll
            for (int k = 0; k < 4; k++) acc[i][j][k] = 0.f;

    const int NC = Kp / BKE;

    // preload iter 0
    {
        cpa16(sAW, gA);       cpa16(sAW + 16, gA + 16);
        cpa16(sBW, gB);       cpa16(sBW + 16, gB + 16);
        asm volatile("cp.async.commit_group;" ::: "memory");
    }

    // ldmatrix lane address components
    int q = lane >> 3, rr8 = lane & 7;
    int a_row = (q & 1) * 8 + rr8;        // + wm + mt*16
    int a_kc  = (q >> 1);                 // + s*2
    int b_row = (q >> 1) * 8 + rr8;       // + wn + pt*16
    int b_kc  = (q & 1);                  // + s*2

    for (int i = 0; i < NC; i++) {
        int buf = i & 1, nbuf = buf ^ 1;
        if (i + 1 < NC) {
            const char* ga = gA + (size_t)(i + 1) * 64;
            const char* gb = gB + (size_t)(i + 1) * 64;
            uint32_t da = s2u(smA[nbuf]) + crow * ROWB + cc0 * 16;
            uint32_t db = s2u(smB[nbuf]) + crow * ROWB + cc0 * 16;
            cpa16(da, ga); cpa16(da + 16, ga + 16);
            cpa16(db, gb); cpa16(db + 16, gb + 16);
        }
        asm volatile("cp.async.commit_group;" ::: "memory");
        asm volatile("cp.async.wait_group 1;" ::: "memory");
        __syncthreads();

        uint32_t sA = s2u(smA[buf]), sB = s2u(smB[buf]);
#pragma unroll
        for (int s = 0; s < 2; s++) {
            uint32_t af[2][4], bq[4][4];
#pragma unroll
            for (int mt = 0; mt < 2; mt++)
                ldsm4(af[mt], sA + (wm + mt * 16 + a_row) * ROWB + (s * 2 + a_kc) * 16);
#pragma unroll
            for (int pt = 0; pt < 4; pt++)
                ldsm4(bq[pt], sB + (wn + pt * 16 + b_row) * ROWB + (s * 2 + b_kc) * 16);
#pragma unroll
            for (int mt = 0; mt < 2; mt++)
#pragma unroll
                for (int pt = 0; pt < 4; pt++) {
                    mma16816(acc[mt][pt * 2 + 0], af[mt], &bq[pt][0]);
                    mma16816(acc[mt][pt * 2 + 1], af[mt], &bq[pt][2]);
                }
        }
        __syncthreads();
    }

    // epilogue: thread (lane) holds rows g, g+8 and cols 2t, 2t+1 of each 16x8 tile
    int g = lane >> 2, t4 = lane & 3;
#pragma unroll
    for (int mt = 0; mt < 2; mt++) {
#pragma unroll
        for (int nt = 0; nt < 8; nt++) {
            int cc = col0 + wn + nt * 8 + t4 * 2;
            if (cc >= N) continue;
            int r1 = row0 + wm + mt * 16 + g;
            int r2 = r1 + 8;
            float v[4] = {acc[mt][nt][0], acc[mt][nt][1], acc[mt][nt][2], acc[mt][nt][3]};
            if (EPI == 1 || EPI == 2) {
                float b0 = bias[cc], b1 = bias[cc + 1];
                v[0] += b0; v[1] += b1; v[2] += b0; v[3] += b1;
            }
            if (EPI == 1) {
#pragma unroll
                for (int e = 0; e < 4; e++)
                    v[e] = 0.5f * v[e] * (1.f + erff(v[e] * 0.70710678118654752f));
            }
            if (EPI == 2 || EPI == 3) {
                v[0] += R[(size_t)r1 * N + cc]; v[1] += R[(size_t)r1 * N + cc + 1];
                v[2] += R[(size_t)r2 * N + cc]; v[3] += R[(size_t)r2 * N + cc + 1];
            }
            *(float2*)&C[(size_t)r1 * N + cc] = make_float2(v[0], v[1]);
            *(float2*)&C[(size_t)r2 * N + cc] = make_float2(v[2], v[3]);
        }
    }
}

// ---------------------------------------------------------------------------
// Block reduce (256 threads) of two values
// ---------------------------------------------------------------------------
__device__ __forceinline__ float2 block_reduce2(float a, float b) {
    __shared__ float sa[8], sb_[8];
    int lane = threadIdx.x & 31, w = threadIdx.x >> 5;
#pragma unroll
    for (int o = 16; o; o >>= 1) {
        a += __shfl_xor_sync(0xffffffffu, a, o);
        b += __shfl_xor_sync(0xffffffffu, b, o);
    }
    __syncthreads();
    if (lane == 0) { sa[w] = a; sb_[w] = b; }
    __syncthreads();
    float ta = 0.f, tb = 0.f;
#pragma unroll
    for (int i = 0; i < 8; i++) { ta += sa[i]; tb += sb_[i]; }
    return make_float2(ta, tb);
}

// ---------------------------------------------------------------------------
// LN0 -> LN1 fused
// ---------------------------------------------------------------------------
__global__ void ln01_kernel(const float* __restrict__ x,
                            const float* __restrict__ w0, const float* __restrict__ b0,
                            const float* __restrict__ w1, const float* __restrict__ b1) {
    int row = blockIdx.x, t = threadIdx.x;
    float4 v = *(const float4*)(x + (size_t)row * DM + t * 4);
    float s = v.x + v.y + v.z + v.w;
    float ss = v.x*v.x + v.y*v.y + v.z*v.z + v.w*v.w;
    float2 r0 = block_reduce2(s, ss);
    float mean = r0.x * (1.f / DM);
    float var = r0.y * (1.f / DM) - mean * mean;
    float rs = rsqrtf(var + 1e-5f);
    int c = t * 4;
    float y0 = (v.x - mean) * rs * w0[c+0] + b0[c+0];
    float y1 = (v.y - mean) * rs * w0[c+1] + b0[c+1];
    float y2 = (v.z - mean) * rs * w0[c+2] + b0[c+2];
    float y3 = (v.w - mean) * rs * w0[c+3] + b0[c+3];
    *(float4*)(g_x0 + (size_t)row * DM + c) = make_float4(y0, y1, y2, y3);
    s = y0 + y1 + y2 + y3;
    ss = y0*y0 + y1*y1 + y2*y2 + y3*y3;
    float2 r1 = block_reduce2(s, ss);
    mean = r1.x * (1.f / DM);
    var = r1.y * (1.f / DM) - mean * mean;
    rs = rsqrtf(var + 1e-5f);
    float u0 = (y0 - mean) * rs * w1[c+0] + b1[c+0];
    float u1 = (y1 - mean) * rs * w1[c+1] + b1[c+1];
    float u2 = (y2 - mean) * rs * w1[c+2] + b1[c+2];
    float u3 = (y3 - mean) * rs * w1[c+3] + b1[c+3];
    *(float4*)(g_u + (size_t)row * DM + c) = make_float4(u0, u1, u2, u3);
}

__global__ void ln2_kernel(const float* __restrict__ w, const float* __restrict__ b) {
    int row = blockIdx.x, t = threadIdx.x;
    float4 v = *(const float4*)(g_x1 + (size_t)row * DM + t * 4);
    float s = v.x + v.y + v.z + v.w;
    float ss = v.x*v.x + v.y*v.y + v.z*v.z + v.w*v.w;
    float2 r0 = block_reduce2(s, ss);
    float mean = r0.x * (1.f / DM);
    float var = r0.y * (1.f / DM) - mean * mean;
    float rs = rsqrtf(var + 1e-5f);
    int c = t * 4;
    float4 o;
    o.x = (v.x - mean) * rs * w[c+0] + b[c+0];
    o.y = (v.y - mean) * rs * w[c+1] + b[c+1];
    o.z = (v.z - mean) * rs * w[c+2] + b[c+2];
    o.w = (v.w - mean) * rs * w[c+3] + b[c+3];
    *(float4*)(g_hln + (size_t)row * DM + c) = o;
}

// ---------------------------------------------------------------------------
// Causal depthwise conv (k=4) + silu
// ---------------------------------------------------------------------------
__global__ void conv_silu_kernel(const float* __restrict__ cw, const float* __restrict__ cb) {
    int c = blockIdx.x * blockDim.x + threadIdx.x;
    if (c >= CONVD) return;
    int r = blockIdx.y;
    int b = r >> 11, l = r & (SEQ - 1);
    float w0 = cw[c*4+0], w1 = cw[c*4+1], w2 = cw[c*4+2], w3 = cw[c*4+3];
    const float* base = g_zx + (size_t)(b * SEQ) * DIP + DI + c;
    float acc = cb[c];
    if (l >= 3) acc = fmaf(w0, base[(size_t)(l-3) * DIP], acc);
    if (l >= 2) acc = fmaf(w1, base[(size_t)(l-2) * DIP], acc);
    if (l >= 1) acc = fmaf(w2, base[(size_t)(l-1) * DIP], acc);
    acc = fmaf(w3, base[(size_t)l * DIP], acc);
    g_xc[(size_t)r * CONVD + c] = acc / (1.f + expf(-acc));
}

__global__ void dt_kernel(const float* __restrict__ dt_bias, const float* __restrict__ A_log) {
    int i = blockIdx.x * blockDim.x + threadIdx.x;
    int r = i >> 5, hh = i & 31;
    float raw = g_zx[(size_t)r * DIP + (DI + CONVD) + hh];
    float v = raw + dt_bias[hh];
    float sp = (v > 20.f) ? v : log1pf(expf(v));
    g_dt[i] = sp;
    g_dA[i] = expf(-expf(A_log[hh]) * sp);
}

// ---------------------------------------------------------------------------
// Selective scan: one CTA per (b,h)
// ---------------------------------------------------------------------------
__global__ __launch_bounds__(512, 1)
void scan_kernel(const float* __restrict__ Dp) {
    int bh = blockIdx.x;
    int b = bh >> 5, h = bh & 31;
    int tid = threadIdx.x;
    int p = tid >> 3, sub = tid & 7, n0 = sub << 3;

    __shared__ __align__(16) float sx[2][64];
    __shared__ __align__(16) float sB[2][64];
    __shared__ __align__(16) float sC[2][64];
    __shared__ float sdt[2][2];

    float hs[8];
#pragma unroll
    for (int i = 0; i < 8; i++) hs[i] = 0.f;
    float Dv = Dp[h];

    const float* xcb = g_xc + (size_t)(b * SEQ) * CONVD;
    float* yb = g_ydp + (size_t)(b * SEQ) * DI;

    for (int l = 0; l < SEQ; l++) {
        int buf = l & 1;
        const float* xr = xcb + (size_t)l * CONVD;
        if (tid < 64)        sx[buf][tid]       = xr[h * 64 + tid];
        else if (tid < 128)  sB[buf][tid - 64]  = xr[2048 + (tid - 64)];
        else if (tid < 192)  sC[buf][tid - 128] = xr[2112 + (tid - 128)];
        else if (tid == 192) {
            int ri = (b * SEQ + l) * NH + h;
            sdt[buf][0] = g_dt[ri];
            sdt[buf][1] = g_dA[ri];
        }
        __syncthreads();

        float dtv = sdt[buf][0], dAv = sdt[buf][1];
        float xv = sx[buf][p];
        float dtx = dtv * xv;
        float4 Bv0 = *(const float4*)&sB[buf][n0];
        float4 Bv1 = *(const float4*)&sB[buf][n0 + 4];
        float4 Cv0 = *(const float4*)&sC[buf][n0];
        float4 Cv1 = *(const float4*)&sC[buf][n0 + 4];

        float part;
        hs[0] = fmaf(hs[0], dAv, dtx * Bv0.x); part  = hs[0] * Cv0.x;
        hs[1] = fmaf(hs[1], dAv, dtx * Bv0.y); part += hs[1] * Cv0.y;
        hs[2] = fmaf(hs[2], dAv, dtx * Bv0.z); part += hs[2] * Cv0.z;
        hs[3] = fmaf(hs[3], dAv, dtx * Bv0.w); part += hs[3] * Cv0.w;
        hs[4] = fmaf(hs[4], dAv, dtx * Bv1.x); part += hs[4] * Cv1.x;
        hs[5] = fmaf(hs[5], dAv, dtx * Bv1.y); part += hs[5] * Cv1.y;
        hs[6] = fmaf(hs[6], dAv, dtx * Bv1.z); part += hs[6] * Cv1.z;
        hs[7] = fmaf(hs[7], dAv, dtx * Bv1.w); part += hs[7] * Cv1.w;

        part += __shfl_xor_sync(0xffffffffu, part, 1);
        part += __shfl_xor_sync(0xffffffffu, part, 2);
        part += __shfl_xor_sync(0xffffffffu, part, 4);

        if (sub == 0)
            yb[(size_t)l * DI + h * 64 + p] = fmaf(Dv, xv, part);
    }
}

// ---------------------------------------------------------------------------
// Gate + RMSNorm
// ---------------------------------------------------------------------------
__global__ void gate_rms_kernel(const float* __restrict__ norm_w) {
    int row = blockIdx.x, t = threadIdx.x;
    const float* zr = g_zx + (size_t)row * DIP;
    const float* yr = g_ydp + (size_t)row * DI;
    int c0 = t * 8;
    float g[8];
    float ss = 0.f;
#pragma unroll
    for (int k = 0; k < 2; k++) {
        float4 zv = *(const float4*)(zr + c0 + k * 4);
        float4 yv = *(const float4*)(yr + c0 + k * 4);
        float g0 = yv.x * (zv.x / (1.f + expf(-zv.x)));
        float g1 = yv.y * (zv.y / (1.f + expf(-zv.y)));
        float g2 = yv.z * (zv.z / (1.f + expf(-zv.z)));
        float g3 = yv.w * (zv.w / (1.f + expf(-zv.w)));
        g[k*4+0] = g0; g[k*4+1] = g1; g[k*4+2] = g2; g[k*4+3] = g3;
        ss += g0*g0 + g1*g1 + g2*g2 + g3*g3;
    }
    float2 r = block_reduce2(ss, 0.f);
    float rs = rsqrtf(r.x * (1.f / DI) + 1e-5f);
    float* outr = g_yn + (size_t)row * DI;
#pragma unroll
    for (int k = 0; k < 2; k++) {
        float4 o;
        o.x = g[k*4+0] * rs * norm_w[c0 + k*4+0];
        o.y = g[k*4+1] * rs * norm_w[c0 + k*4+1];
        o.z = g[k*4+2] * rs * norm_w[c0 + k*4+2];
        o.w = g[k*4+3] * rs * norm_w[c0 + k*4+3];
        *(float4*)(outr + c0 + k*4) = o;
    }
}

// ---------------------------------------------------------------------------
// Host launcher
// ---------------------------------------------------------------------------
extern "C" void kernel_launch(void* const* d_in, const int* in_sizes, int n_in,
                              void* d_out, int out_size) {
    const float* x         = (const float*)d_in[0];
    const float* ln0_w     = (const float*)d_in[1];
    const float* ln0_b     = (const float*)d_in[2];
    const float* ln1_w     = (const float*)d_in[3];
    const float* ln1_b     = (const float*)d_in[4];
    const float* ln2_w     = (const float*)d_in[5];
    const float* ln2_b     = (const float*)d_in[6];
    const float* in_proj_w = (const float*)d_in[7];
    const float* conv_w    = (const float*)d_in[8];
    const float* conv_b    = (const float*)d_in[9];
    const float* dt_bias   = (const float*)d_in[10];
    const float* A_log     = (const float*)d_in[11];
    const float* D_param   = (const float*)d_in[12];
    const float* norm_w    = (const float*)d_in[13];
    const float* out_proj_w= (const float*)d_in[14];
    const float* ffn_w1    = (const float*)d_in[15];
    const float* ffn_b1    = (const float*)d_in[16];
    const float* ffn_w2    = (const float*)d_in[17];
    const float* ffn_b2    = (const float*)d_in[18];
    float* out = (float*)d_out;

    float *pu, *px0, *pzx, *pyn, *px1, *phln, *pt;
    __nv_bfloat16 *pa2, *pb2;
    cudaGetSymbolAddress((void**)&pu,   g_u);
    cudaGetSymbolAddress((void**)&px0,  g_x0);
    cudaGetSymbolAddress((void**)&pzx,  g_zx);
    cudaGetSymbolAddress((void**)&pyn,  g_yn);
    cudaGetSymbolAddress((void**)&px1,  g_x1);
    cudaGetSymbolAddress((void**)&phln, g_hln);
    cudaGetSymbolAddress((void**)&pt,   g_t);
    cudaGetSymbolAddress((void**)&pa2,  g_a2);
    cudaGetSymbolAddress((void**)&pb2,  g_b2);

    // 1. LN0 + LN1
    ln01_kernel<<<MROWS, 256>>>(x, ln0_w, ln0_b, ln1_w, ln1_b);

    // 2. in_proj: [4096,1024] x [4256,1024]^T  (split-bf16, Npad=4352, Kp=3072)
    cvt_act<<<(MROWS * DM) / 256, 256>>>(pu, pa2, DM);
    cvt_wt<<<(4352 * DM) / 256, 256>>>(in_proj_w, pb2, DIP, DM);
    gemm_mma<0><<<dim3(4352 / BN, MROWS / BM), 256>>>(
        pa2, pb2, pzx, nullptr, nullptr, DIP, 3 * DM);

    // 3-6. conv, dt, scan, gate
    conv_silu_kernel<<<dim3((CONVD + 255) / 256, MROWS), 256>>>(conv_w, conv_b);
    dt_kernel<<<(MROWS * NH) / 256, 256>>>(dt_bias, A_log);
    scan_kernel<<<B_SZ * NH, 512>>>(D_param);
    gate_rms_kernel<<<MROWS, 256>>>(norm_w);

    // 7. out_proj + residual(x0) -> x1  (Kp=6144)
    cvt_act<<<(MROWS * DI) / 256, 256>>>(pyn, pa2, DI);
    cvt_wt<<<(1024 * DI) / 256, 256>>>(out_proj_w, pb2, DM, DI);
    gemm_mma<3><<<dim3(DM / BN, MROWS / BM), 256>>>(
        pa2, pb2, px1, nullptr, px0, DM, 3 * DI);

    // 8. LN2
    ln2_kernel<<<MROWS, 256>>>(ln2_w, ln2_b);

    // 9. FFN1 + bias + gelu  (Kp=3072)
    cvt_act<<<(MROWS * DM) / 256, 256>>>(phln, pa2, DM);
    cvt_wt<<<(FFN * DM) / 256, 256>>>(ffn_w1, pb2, FFN, DM);
    gemm_mma<1><<<dim3(FFN / BN, MROWS / BM), 256>>>(
        pa2, pb2, pt, ffn_b1, nullptr, FFN, 3 * DM);

    // 10. FFN2 + bias + residual(x1) -> out  (Kp=12288)
    cvt_act<<<(MROWS * FFN) / 256, 256>>>(pt, pa2, FFN);
    cvt_wt<<<(1024 * FFN) / 256, 256>>>(ffn_w2, pb2, DM, FFN);
    gemm_mma<2><<<dim3(DM / BN, MROWS / BM), 256>>>(
        pa2, pb2, out, ffn_b2, px1, DM, 3 * FFN);
}

// round 12
// speedup vs baseline: 1.8054x; 1.2824x over previous
#include <cuda_runtime.h>
#include <cuda_bf16.h>
#include <math.h>
#include <stdint.h>

// ---------------------------------------------------------------------------
// Shapes
// ---------------------------------------------------------------------------
#define B_SZ   2
#define SEQ    2048
#define MROWS  4096
#define DM     1024
#define DI     2048
#define CONVD  2176
#define DIP    4256
#define NH     32
#define FFN    4096

// scan chunking
#define NCH    16          // chunks per sequence
#define CHL    128         // chunk length
#define NTASK  (B_SZ * NH * NCH)   // 1024

// GEMM tiling (mma.sync path)
#define BM     128
#define BN     128
#define BKE    64          // bf16 elems per K iteration (128B per row)
#define ROWB   144         // smem bytes per row (128B data + 16B skew)
#define TILEB  (128 * ROWB)        // 18432
#define GSMEM  (4 * TILEB)         // 73728 dynamic smem

// ---------------------------------------------------------------------------
// Scratch (static device globals; no allocation allowed)
// ---------------------------------------------------------------------------
__device__ __align__(256) float g_x0 [MROWS * DM];
__device__ __align__(256) float g_u  [MROWS * DM];
__device__ __align__(256) float g_zx [MROWS * DIP];
__device__ __align__(256) float g_xc [MROWS * CONVD];
__device__ __align__(256) float g_dt [MROWS * NH];
__device__ __align__(256) float g_dA [MROWS * NH];
__device__ __align__(256) float g_ydp[MROWS * DI];
__device__ __align__(256) float g_yn [MROWS * DI];
__device__ __align__(256) float g_x1 [MROWS * DM];
__device__ __align__(256) float g_hln[MROWS * DM];
__device__ __align__(256) float g_t  [MROWS * FFN];
// scan chunk scratch
__device__ __align__(256) float g_cp [MROWS * NH];          // per-step cumprod within chunk
__device__ __align__(256) float g_S  [(size_t)NTASK * 4096]; // chunk-final local states
__device__ __align__(256) float g_Hin[(size_t)NTASK * 4096]; // chunk incoming states
// split-bf16 staging
__device__ __align__(256) __nv_bfloat16 g_a2[(size_t)MROWS * 12288];
__device__ __align__(256) __nv_bfloat16 g_b2[(size_t)4352 * 3072];

// ---------------------------------------------------------------------------
// Helpers
// ---------------------------------------------------------------------------
__device__ __forceinline__ uint32_t s2u(const void* p) {
    uint32_t r;
    asm("{ .reg .u64 t; cvta.to.shared.u64 t, %1; cvt.u32.u64 %0, t; }" : "=r"(r) : "l"(p));
    return r;
}
__device__ __forceinline__ void cpa16(uint32_t dst, const void* src) {
    asm volatile("cp.async.cg.shared.global [%0], [%1], 16;" :: "r"(dst), "l"(src));
}
__device__ __forceinline__ void ldsm4(uint32_t* r, uint32_t a) {
    asm volatile("ldmatrix.sync.aligned.m8n8.x4.shared.b16 {%0,%1,%2,%3}, [%4];"
                 : "=r"(r[0]), "=r"(r[1]), "=r"(r[2]), "=r"(r[3]) : "r"(a));
}
__device__ __forceinline__ void mma16816(float* d, const uint32_t* a, const uint32_t* b) {
    asm volatile("mma.sync.aligned.m16n8k16.row.col.f32.bf16.bf16.f32 "
                 "{%0,%1,%2,%3}, {%4,%5,%6,%7}, {%8,%9}, {%0,%1,%2,%3};"
                 : "+f"(d[0]), "+f"(d[1]), "+f"(d[2]), "+f"(d[3])
                 : "r"(a[0]), "r"(a[1]), "r"(a[2]), "r"(a[3]), "r"(b[0]), "r"(b[1]));
}

// ---------------------------------------------------------------------------
// split-bf16 conversion kernels (vectorized: float4 in, bf16x2 out)
// act: [hi | lo | hi] along K' = 3K     wt: [hi | hi | lo], rows >= Nreal zeroed
// ---------------------------------------------------------------------------
__global__ void cvt_act(const float* __restrict__ src, __nv_bfloat16* __restrict__ dst, int K) {
    int idx = (blockIdx.x * blockDim.x + threadIdx.x) * 4;   // over MROWS*K
    int row = idx / K, k = idx - row * K;
    float4 v = *(const float4*)(src + idx);
    __nv_bfloat16 h0 = __float2bfloat16(v.x), h1 = __float2bfloat16(v.y);
    __nv_bfloat16 h2 = __float2bfloat16(v.z), h3 = __float2bfloat16(v.w);
    __nv_bfloat16 l0 = __float2bfloat16(v.x - __bfloat162float(h0));
    __nv_bfloat16 l1 = __float2bfloat16(v.y - __bfloat162float(h1));
    __nv_bfloat16 l2 = __float2bfloat16(v.z - __bfloat162float(h2));
    __nv_bfloat16 l3 = __float2bfloat16(v.w - __bfloat162float(h3));
    size_t b = (size_t)row * 3 * K;
    __nv_bfloat162* p0 = (__nv_bfloat162*)(dst + b + k);
    __nv_bfloat162* p1 = (__nv_bfloat162*)(dst + b + K + k);
    __nv_bfloat162* p2 = (__nv_bfloat162*)(dst + b + 2 * K + k);
    p0[0] = __halves2bfloat162(h0, h1); p0[1] = __halves2bfloat162(h2, h3);
    p1[0] = __halves2bfloat162(l0, l1); p1[1] = __halves2bfloat162(l2, l3);
    p2[0] = __halves2bfloat162(h0, h1); p2[1] = __halves2bfloat162(h2, h3);
}
__global__ void cvt_wt(const float* __restrict__ src, __nv_bfloat16* __restrict__ dst,
                       int Nreal, int K) {
    int idx = (blockIdx.x * blockDim.x + threadIdx.x) * 4;   // over Npad*K
    int row = idx / K, k = idx - row * K;
    float4 v = make_float4(0.f, 0.f, 0.f, 0.f);
    if (row < Nreal) v = *(const float4*)(src + (size_t)row * K + k);
    __nv_bfloat16 h0 = __float2bfloat16(v.x), h1 = __float2bfloat16(v.y);
    __nv_bfloat16 h2 = __float2bfloat16(v.z), h3 = __float2bfloat16(v.w);
    __nv_bfloat16 l0 = __float2bfloat16(v.x - __bfloat162float(h0));
    __nv_bfloat16 l1 = __float2bfloat16(v.y - __bfloat162float(h1));
    __nv_bfloat16 l2 = __float2bfloat16(v.z - __bfloat162float(h2));
    __nv_bfloat16 l3 = __float2bfloat16(v.w - __bfloat162float(h3));
    size_t b = (size_t)row * 3 * K;
    __nv_bfloat162* p0 = (__nv_bfloat162*)(dst + b + k);
    __nv_bfloat162* p1 = (__nv_bfloat162*)(dst + b + K + k);
    __nv_bfloat162* p2 = (__nv_bfloat162*)(dst + b + 2 * K + k);
    p0[0] = __halves2bfloat162(h0, h1); p0[1] = __halves2bfloat162(h2, h3);
    p1[0] = __halves2bfloat162(h0, h1); p1[1] = __halves2bfloat162(h2, h3);
    p2[0] = __halves2bfloat162(l0, l1); p2[1] = __halves2bfloat162(l2, l3);
}

// ---------------------------------------------------------------------------
// bf16 mma.sync GEMM: C[M,N] = A2[M,Kp] * B2[Npad,Kp]^T, fp32 accumulate
// EPI: 0 none, 1 bias+gelu, 2 bias+residual, 3 residual
// 128x128x64 tile, 256 threads (8 warps, 4x2), warp tile 32x64, m16n8k16
// ---------------------------------------------------------------------------
template<int EPI>
__global__ __launch_bounds__(256, 2)
void gemm_mma(const __nv_bfloat16* __restrict__ A2, const __nv_bfloat16* __restrict__ B2,
              float* __restrict__ C, const float* __restrict__ bias,
              const float* __restrict__ R, int N, int Kp) {
    extern __shared__ char dynsm[];
    char (*smA)[TILEB] = (char(*)[TILEB])dynsm;
    char (*smB)[TILEB] = (char(*)[TILEB])(dynsm + 2 * TILEB);

    int tid = threadIdx.x, lane = tid & 31, wid = tid >> 5;
    int row0 = blockIdx.y * BM, col0 = blockIdx.x * BN;
    int wm = (wid & 3) * 32, wn = (wid >> 2) * 64;

    // cp.async: per stage 128 rows x 8 x 16B per operand; thread: row=tid/2, 4 chunks
    int crow = tid >> 1;
    int cc0  = (tid & 1) * 4;             // chunk 0..3 or 4..7
    size_t KpB = (size_t)Kp * 2;
    const char* gA = (const char*)A2 + (size_t)(row0 + crow) * KpB + cc0 * 16;
    const char* gB = (const char*)B2 + (size_t)(col0 + crow) * KpB + cc0 * 16;
    uint32_t sAo = crow * ROWB + cc0 * 16;

    float acc[2][8][4];
#pragma unroll
    for (int i = 0; i < 2; i++)
#pragma unroll
        for (int j = 0; j < 8; j++)
#pragma unroll
            for (int k = 0; k < 4; k++) acc[i][j][k] = 0.f;

    const int NC = Kp / BKE;

    // preload stage 0
    {
        uint32_t da = s2u(smA[0]) + sAo, db = s2u(smB[0]) + sAo;
#pragma unroll
        for (int j = 0; j < 4; j++) { cpa16(da + j * 16, gA + j * 16); }
#pragma unroll
        for (int j = 0; j < 4; j++) { cpa16(db + j * 16, gB + j * 16); }
        asm volatile("cp.async.commit_group;" ::: "memory");
    }

    // ldmatrix lane address components
    int q = lane >> 3, rr8 = lane & 7;
    int a_row = (q & 1) * 8 + rr8;
    int a_kc  = (q >> 1);
    int b_row = (q >> 1) * 8 + rr8;
    int b_kc  = (q & 1);

    for (int i = 0; i < NC; i++) {
        int buf = i & 1, nbuf = buf ^ 1;
        if (i + 1 < NC) {
            const char* ga = gA + (size_t)(i + 1) * 128;
            const char* gb = gB + (size_t)(i + 1) * 128;
            uint32_t da = s2u(smA[nbuf]) + sAo, db = s2u(smB[nbuf]) + sAo;
#pragma unroll
            for (int j = 0; j < 4; j++) { cpa16(da + j * 16, ga + j * 16); }
#pragma unroll
            for (int j = 0; j < 4; j++) { cpa16(db + j * 16, gb + j * 16); }
        }
        asm volatile("cp.async.commit_group;" ::: "memory");
        asm volatile("cp.async.wait_group 1;" ::: "memory");
        __syncthreads();

        uint32_t sA = s2u(smA[buf]), sB = s2u(smB[buf]);
#pragma unroll
        for (int s = 0; s < 4; s++) {
            uint32_t af[2][4], bq[4][4];
#pragma unroll
            for (int mt = 0; mt < 2; mt++)
                ldsm4(af[mt], sA + (wm + mt * 16 + a_row) * ROWB + (s * 2 + a_kc) * 16);
#pragma unroll
            for (int pt = 0; pt < 4; pt++)
                ldsm4(bq[pt], sB + (wn + pt * 16 + b_row) * ROWB + (s * 2 + b_kc) * 16);
#pragma unroll
            for (int mt = 0; mt < 2; mt++)
#pragma unroll
                for (int pt = 0; pt < 4; pt++) {
                    mma16816(acc[mt][pt * 2 + 0], af[mt], &bq[pt][0]);
                    mma16816(acc[mt][pt * 2 + 1], af[mt], &bq[pt][2]);
                }
        }
        __syncthreads();
    }

    // epilogue
    int g = lane >> 2, t4 = lane & 3;
#pragma unroll
    for (int mt = 0; mt < 2; mt++) {
#pragma unroll
        for (int nt = 0; nt < 8; nt++) {
            int cc = col0 + wn + nt * 8 + t4 * 2;
            if (cc >= N) continue;
            int r1 = row0 + wm + mt * 16 + g;
            int r2 = r1 + 8;
            float v[4] = {acc[mt][nt][0], acc[mt][nt][1], acc[mt][nt][2], acc[mt][nt][3]};
            if (EPI == 1 || EPI == 2) {
                float b0 = bias[cc], b1 = bias[cc + 1];
                v[0] += b0; v[1] += b1; v[2] += b0; v[3] += b1;
            }
            if (EPI == 1) {
#pragma unroll
                for (int e = 0; e < 4; e++)
                    v[e] = 0.5f * v[e] * (1.f + erff(v[e] * 0.70710678118654752f));
            }
            if (EPI == 2 || EPI == 3) {
                v[0] += R[(size_t)r1 * N + cc]; v[1] += R[(size_t)r1 * N + cc + 1];
                v[2] += R[(size_t)r2 * N + cc]; v[3] += R[(size_t)r2 * N + cc + 1];
            }
            *(float2*)&C[(size_t)r1 * N + cc] = make_float2(v[0], v[1]);
            *(float2*)&C[(size_t)r2 * N + cc] = make_float2(v[2], v[3]);
        }
    }
}

// ---------------------------------------------------------------------------
// Block reduce (256 threads) of two values
// ---------------------------------------------------------------------------
__device__ __forceinline__ float2 block_reduce2(float a, float b) {
    __shared__ float sa[8], sb_[8];
    int lane = threadIdx.x & 31, w = threadIdx.x >> 5;
#pragma unroll
    for (int o = 16; o; o >>= 1) {
        a += __shfl_xor_sync(0xffffffffu, a, o);
        b += __shfl_xor_sync(0xffffffffu, b, o);
    }
    __syncthreads();
    if (lane == 0) { sa[w] = a; sb_[w] = b; }
    __syncthreads();
    float ta = 0.f, tb = 0.f;
#pragma unroll
    for (int i = 0; i < 8; i++) { ta += sa[i]; tb += sb_[i]; }
    return make_float2(ta, tb);
}

// ---------------------------------------------------------------------------
// LN0 -> LN1 fused
// ---------------------------------------------------------------------------
__global__ void ln01_kernel(const float* __restrict__ x,
                            const float* __restrict__ w0, const float* __restrict__ b0,
                            const float* __restrict__ w1, const float* __restrict__ b1) {
    int row = blockIdx.x, t = threadIdx.x;
    float4 v = *(const float4*)(x + (size_t)row * DM + t * 4);
    float s = v.x + v.y + v.z + v.w;
    float ss = v.x*v.x + v.y*v.y + v.z*v.z + v.w*v.w;
    float2 r0 = block_reduce2(s, ss);
    float mean = r0.x * (1.f / DM);
    float var = r0.y * (1.f / DM) - mean * mean;
    float rs = rsqrtf(var + 1e-5f);
    int c = t * 4;
    float y0 = (v.x - mean) * rs * w0[c+0] + b0[c+0];
    float y1 = (v.y - mean) * rs * w0[c+1] + b0[c+1];
    float y2 = (v.z - mean) * rs * w0[c+2] + b0[c+2];
    float y3 = (v.w - mean) * rs * w0[c+3] + b0[c+3];
    *(float4*)(g_x0 + (size_t)row * DM + c) = make_float4(y0, y1, y2, y3);
    s = y0 + y1 + y2 + y3;
    ss = y0*y0 + y1*y1 + y2*y2 + y3*y3;
    float2 r1 = block_reduce2(s, ss);
    mean = r1.x * (1.f / DM);
    var = r1.y * (1.f / DM) - mean * mean;
    rs = rsqrtf(var + 1e-5f);
    float u0 = (y0 - mean) * rs * w1[c+0] + b1[c+0];
    float u1 = (y1 - mean) * rs * w1[c+1] + b1[c+1];
    float u2 = (y2 - mean) * rs * w1[c+2] + b1[c+2];
    float u3 = (y3 - mean) * rs * w1[c+3] + b1[c+3];
    *(float4*)(g_u + (size_t)row * DM + c) = make_float4(u0, u1, u2, u3);
}

__global__ void ln2_kernel(const float* __restrict__ w, const float* __restrict__ b) {
    int row = blockIdx.x, t = threadIdx.x;
    float4 v = *(const float4*)(g_x1 + (size_t)row * DM + t * 4);
    float s = v.x + v.y + v.z + v.w;
    float ss = v.x*v.x + v.y*v.y + v.z*v.z + v.w*v.w;
    float2 r0 = block_reduce2(s, ss);
    float mean = r0.x * (1.f / DM);
    float var = r0.y * (1.f / DM) - mean * mean;
    float rs = rsqrtf(var + 1e-5f);
    int c = t * 4;
    float4 o;
    o.x = (v.x - mean) * rs * w[c+0] + b[c+0];
    o.y = (v.y - mean) * rs * w[c+1] + b[c+1];
    o.z = (v.z - mean) * rs * w[c+2] + b[c+2];
    o.w = (v.w - mean) * rs * w[c+3] + b[c+3];
    *(float4*)(g_hln + (size_t)row * DM + c) = o;
}

// ---------------------------------------------------------------------------
// Causal depthwise conv (k=4) + silu
// ---------------------------------------------------------------------------
__global__ void conv_silu_kernel(const float* __restrict__ cw, const float* __restrict__ cb) {
    int c = blockIdx.x * blockDim.x + threadIdx.x;
    if (c >= CONVD) return;
    int r = blockIdx.y;
    int b = r >> 11, l = r & (SEQ - 1);
    float w0 = cw[c*4+0], w1 = cw[c*4+1], w2 = cw[c*4+2], w3 = cw[c*4+3];
    const float* base = g_zx + (size_t)(b * SEQ) * DIP + DI + c;
    float acc = cb[c];
    if (l >= 3) acc = fmaf(w0, base[(size_t)(l-3) * DIP], acc);
    if (l >= 2) acc = fmaf(w1, base[(size_t)(l-2) * DIP], acc);
    if (l >= 1) acc = fmaf(w2, base[(size_t)(l-1) * DIP], acc);
    acc = fmaf(w3, base[(size_t)l * DIP], acc);
    g_xc[(size_t)r * CONVD + c] = acc / (1.f + expf(-acc));
}

__global__ void dt_kernel(const float* __restrict__ dt_bias, const float* __restrict__ A_log) {
    int i = blockIdx.x * blockDim.x + threadIdx.x;
    int r = i >> 5, hh = i & 31;
    float raw = g_zx[(size_t)r * DIP + (DI + CONVD) + hh];
    float v = raw + dt_bias[hh];
    float sp = (v > 20.f) ? v : log1pf(expf(v));
    g_dt[i] = sp;
    g_dA[i] = expf(-expf(A_log[hh]) * sp);
}

// ---------------------------------------------------------------------------
// Chunked selective scan
// Phase 1: one CTA per (b,h,chunk). From h=0: y_local (incl D*x), per-step
//          cumprod cp_l, chunk-final state S.
// ---------------------------------------------------------------------------
__global__ __launch_bounds__(512, 1)
void scan_ph1(const float* __restrict__ Dp) {
    int t = blockIdx.x;                     // ((b*NH + h)*NCH + c)
    int c = t & (NCH - 1);
    int bh = t >> 4;
    int b = bh >> 5, h = bh & 31;
    int tid = threadIdx.x;
    int p = tid >> 3, sub = tid & 7, n0 = sub << 3;
    int l0 = c * CHL;

    __shared__ __align__(16) float sx[2][64];
    __shared__ __align__(16) float sB[2][64];
    __shared__ __align__(16) float sC[2][64];
    __shared__ float sdt[2][2];

    float hs[8];
#pragma unroll
    for (int i = 0; i < 8; i++) hs[i] = 0.f;
    float Dv = Dp[h];
    float cp = 1.f;

    const float* xcb = g_xc + (size_t)(b * SEQ) * CONVD;
    float* yb = g_ydp + (size_t)(b * SEQ) * DI;

    for (int ll = 0; ll < CHL; ll++) {
        int l = l0 + ll;
        int buf = ll & 1;
        const float* xr = xcb + (size_t)l * CONVD;
        int ri = (b * SEQ + l) * NH + h;
        if (tid < 64)        sx[buf][tid]       = xr[h * 64 + tid];
        else if (tid < 128)  sB[buf][tid - 64]  = xr[2048 + (tid - 64)];
        else if (tid < 192)  sC[buf][tid - 128] = xr[2112 + (tid - 128)];
        else if (tid == 192) {
            sdt[buf][0] = g_dt[ri];
            sdt[buf][1] = g_dA[ri];
        }
        __syncthreads();

        float dtv = sdt[buf][0], dAv = sdt[buf][1];
        cp *= dAv;
        if (tid == 0) g_cp[ri] = cp;
        float xv = sx[buf][p];
        float dtx = dtv * xv;
        float4 Bv0 = *(const float4*)&sB[buf][n0];
        float4 Bv1 = *(const float4*)&sB[buf][n0 + 4];
        float4 Cv0 = *(const float4*)&sC[buf][n0];
        float4 Cv1 = *(const float4*)&sC[buf][n0 + 4];

        float part;
        hs[0] = fmaf(hs[0], dAv, dtx * Bv0.x); part  = hs[0] * Cv0.x;
        hs[1] = fmaf(hs[1], dAv, dtx * Bv0.y); part += hs[1] * Cv0.y;
        hs[2] = fmaf(hs[2], dAv, dtx * Bv0.z); part += hs[2] * Cv0.z;
        hs[3] = fmaf(hs[3], dAv, dtx * Bv0.w); part += hs[3] * Cv0.w;
        hs[4] = fmaf(hs[4], dAv, dtx * Bv1.x); part += hs[4] * Cv1.x;
        hs[5] = fmaf(hs[5], dAv, dtx * Bv1.y); part += hs[5] * Cv1.y;
        hs[6] = fmaf(hs[6], dAv, dtx * Bv1.z); part += hs[6] * Cv1.z;
        hs[7] = fmaf(hs[7], dAv, dtx * Bv1.w); part += hs[7] * Cv1.w;

        part += __shfl_xor_sync(0xffffffffu, part, 1);
        part += __shfl_xor_sync(0xffffffffu, part, 2);
        part += __shfl_xor_sync(0xffffffffu, part, 4);

        if (sub == 0)
            yb[(size_t)l * DI + h * 64 + p] = fmaf(Dv, xv, part);
    }

    // store chunk-final local state S[p][n]
    float* Sp = g_S + (size_t)t * 4096 + p * 64 + n0;
    *(float4*)(Sp + 0) = make_float4(hs[0], hs[1], hs[2], hs[3]);
    *(float4*)(Sp + 4) = make_float4(hs[4], hs[5], hs[6], hs[7]);
}

// Phase 2: one CTA per (b,h); 16-step chunk recurrence over 64x64 states.
__global__ __launch_bounds__(512, 1)
void scan_ph2() {
    int bh = blockIdx.x;
    int b = bh >> 5, h = bh & 31;
    int e = threadIdx.x * 8;
    float H[8];
#pragma unroll
    for (int i = 0; i < 8; i++) H[i] = 0.f;

    for (int c = 0; c < NCH; c++) {
        size_t t = (size_t)(bh * NCH + c);
        float* dst = g_Hin + t * 4096 + e;
        *(float4*)(dst + 0) = make_float4(H[0], H[1], H[2], H[3]);
        *(float4*)(dst + 4) = make_float4(H[4], H[5], H[6], H[7]);
        float cpT = g_cp[(b * SEQ + c * CHL + CHL - 1) * NH + h];
        const float* Sp = g_S + t * 4096 + e;
        float4 s0 = *(const float4*)(Sp + 0);
        float4 s1 = *(const float4*)(Sp + 4);
        H[0] = fmaf(cpT, H[0], s0.x); H[1] = fmaf(cpT, H[1], s0.y);
        H[2] = fmaf(cpT, H[2], s0.z); H[3] = fmaf(cpT, H[3], s0.w);
        H[4] = fmaf(cpT, H[4], s1.x); H[5] = fmaf(cpT, H[5], s1.y);
        H[6] = fmaf(cpT, H[6], s1.z); H[7] = fmaf(cpT, H[7], s1.w);
    }
}

// Phase 3: one CTA per (b,h,chunk). y_l += cp_l * (C_l . H_in[p,:]) — parallel.
__global__ __launch_bounds__(512, 1)
void scan_ph3() {
    int t = blockIdx.x;
    int c = t & (NCH - 1);
    int bh = t >> 4;
    int b = bh >> 5, h = bh & 31;
    int tid = threadIdx.x;
    int p = tid >> 3, sub = tid & 7, n0 = sub << 3;
    int l0 = c * CHL;

    __shared__ __align__(16) float sH[4096];
    {
        const float* src = g_Hin + (size_t)t * 4096 + tid * 8;
        float4 a = *(const float4*)(src + 0);
        float4 bb = *(const float4*)(src + 4);
        *(float4*)&sH[tid * 8 + 0] = a;
        *(float4*)&sH[tid * 8 + 4] = bb;
    }
    __syncthreads();

    float H[8];
#pragma unroll
    for (int i = 0; i < 8; i++) H[i] = sH[p * 64 + n0 + i];

    const float* xcb = g_xc + (size_t)(b * SEQ) * CONVD;
    float* yb = g_ydp + (size_t)(b * SEQ) * DI;

    for (int ll = 0; ll < CHL; ll++) {
        int l = l0 + ll;
        const float* xr = xcb + (size_t)l * CONVD;
        float cp = g_cp[(b * SEQ + l) * NH + h];
        float4 Cv0 = *(const float4*)(xr + 2112 + n0);
        float4 Cv1 = *(const float4*)(xr + 2112 + n0 + 4);
        float part = H[0] * Cv0.x + H[1] * Cv0.y + H[2] * Cv0.z + H[3] * Cv0.w
                   + H[4] * Cv1.x + H[5] * Cv1.y + H[6] * Cv1.z + H[7] * Cv1.w;
        part += __shfl_xor_sync(0xffffffffu, part, 1);
        part += __shfl_xor_sync(0xffffffffu, part, 2);
        part += __shfl_xor_sync(0xffffffffu, part, 4);
        if (sub == 0) {
            size_t yi = (size_t)l * DI + h * 64 + p;
            yb[yi] += cp * part;
        }
    }
}

// ---------------------------------------------------------------------------
// Gate + RMSNorm
// ---------------------------------------------------------------------------
__global__ void gate_rms_kernel(const float* __restrict__ norm_w) {
    int row = blockIdx.x, t = threadIdx.x;
    const float* zr = g_zx + (size_t)row * DIP;
    const float* yr = g_ydp + (size_t)row * DI;
    int c0 = t * 8;
    float g[8];
    float ss = 0.f;
#pragma unroll
    for (int k = 0; k < 2; k++) {
        float4 zv = *(const float4*)(zr + c0 + k * 4);
        float4 yv = *(const float4*)(yr + c0 + k * 4);
        float g0 = yv.x * (zv.x / (1.f + expf(-zv.x)));
        float g1 = yv.y * (zv.y / (1.f + expf(-zv.y)));
        float g2 = yv.z * (zv.z / (1.f + expf(-zv.z)));
        float g3 = yv.w * (zv.w / (1.f + expf(-zv.w)));
        g[k*4+0] = g0; g[k*4+1] = g1; g[k*4+2] = g2; g[k*4+3] = g3;
        ss += g0*g0 + g1*g1 + g2*g2 + g3*g3;
    }
    float2 r = block_reduce2(ss, 0.f);
    float rs = rsqrtf(r.x * (1.f / DI) + 1e-5f);
    float* outr = g_yn + (size_t)row * DI;
#pragma unroll
    for (int k = 0; k < 2; k++) {
        float4 o;
        o.x = g[k*4+0] * rs * norm_w[c0 + k*4+0];
        o.y = g[k*4+1] * rs * norm_w[c0 + k*4+1];
        o.z = g[k*4+2] * rs * norm_w[c0 + k*4+2];
        o.w = g[k*4+3] * rs * norm_w[c0 + k*4+3];
        *(float4*)(outr + c0 + k*4) = o;
    }
}

// ---------------------------------------------------------------------------
// Host launcher
// ---------------------------------------------------------------------------
extern "C" void kernel_launch(void* const* d_in, const int* in_sizes, int n_in,
                              void* d_out, int out_size) {
    const float* x         = (const float*)d_in[0];
    const float* ln0_w     = (const float*)d_in[1];
    const float* ln0_b     = (const float*)d_in[2];
    const float* ln1_w     = (const float*)d_in[3];
    const float* ln1_b     = (const float*)d_in[4];
    const float* ln2_w     = (const float*)d_in[5];
    const float* ln2_b     = (const float*)d_in[6];
    const float* in_proj_w = (const float*)d_in[7];
    const float* conv_w    = (const float*)d_in[8];
    const float* conv_b    = (const float*)d_in[9];
    const float* dt_bias   = (const float*)d_in[10];
    const float* A_log     = (const float*)d_in[11];
    const float* D_param   = (const float*)d_in[12];
    const float* norm_w    = (const float*)d_in[13];
    const float* out_proj_w= (const float*)d_in[14];
    const float* ffn_w1    = (const float*)d_in[15];
    const float* ffn_b1    = (const float*)d_in[16];
    const float* ffn_w2    = (const float*)d_in[17];
    const float* ffn_b2    = (const float*)d_in[18];
    float* out = (float*)d_out;

    float *pu, *px0, *pzx, *pyn, *px1, *phln, *pt;
    __nv_bfloat16 *pa2, *pb2;
    cudaGetSymbolAddress((void**)&pu,   g_u);
    cudaGetSymbolAddress((void**)&px0,  g_x0);
    cudaGetSymbolAddress((void**)&pzx,  g_zx);
    cudaGetSymbolAddress((void**)&pyn,  g_yn);
    cudaGetSymbolAddress((void**)&px1,  g_x1);
    cudaGetSymbolAddress((void**)&phln, g_hln);
    cudaGetSymbolAddress((void**)&pt,   g_t);
    cudaGetSymbolAddress((void**)&pa2,  g_a2);
    cudaGetSymbolAddress((void**)&pb2,  g_b2);

    cudaFuncSetAttribute(gemm_mma<0>, cudaFuncAttributeMaxDynamicSharedMemorySize, GSMEM);
    cudaFuncSetAttribute(gemm_mma<1>, cudaFuncAttributeMaxDynamicSharedMemorySize, GSMEM);
    cudaFuncSetAttribute(gemm_mma<2>, cudaFuncAttributeMaxDynamicSharedMemorySize, GSMEM);
    cudaFuncSetAttribute(gemm_mma<3>, cudaFuncAttributeMaxDynamicSharedMemorySize, GSMEM);

    // 1. LN0 + LN1
    ln01_kernel<<<MROWS, 256>>>(x, ln0_w, ln0_b, ln1_w, ln1_b);

    // 2. in_proj: [4096,1024] x [4256,1024]^T  (split-bf16, Npad=4352, Kp=3072)
    cvt_act<<<(MROWS * DM) / 1024, 256>>>(pu, pa2, DM);
    cvt_wt<<<(4352 * DM) / 1024, 256>>>(in_proj_w, pb2, DIP, DM);
    gemm_mma<0><<<dim3(4352 / BN, MROWS / BM), 256, GSMEM>>>(
        pa2, pb2, pzx, nullptr, nullptr, DIP, 3 * DM);

    // 3-6. conv, dt, chunked scan, gate
    conv_silu_kernel<<<dim3((CONVD + 255) / 256, MROWS), 256>>>(conv_w, conv_b);
    dt_kernel<<<(MROWS * NH) / 256, 256>>>(dt_bias, A_log);
    scan_ph1<<<NTASK, 512>>>(D_param);
    scan_ph2<<<B_SZ * NH, 512>>>();
    scan_ph3<<<NTASK, 512>>>();
    gate_rms_kernel<<<MROWS, 256>>>(norm_w);

    // 7. out_proj + residual(x0) -> x1  (Kp=6144)
    cvt_act<<<(MROWS * DI) / 1024, 256>>>(pyn, pa2, DI);
    cvt_wt<<<(1024 * DI) / 1024, 256>>>(out_proj_w, pb2, DM, DI);
    gemm_mma<3><<<dim3(DM / BN, MROWS / BM), 256, GSMEM>>>(
        pa2, pb2, px1, nullptr, px0, DM, 3 * DI);

    // 8. LN2
    ln2_kernel<<<MROWS, 256>>>(ln2_w, ln2_b);

    // 9. FFN1 + bias + gelu  (Kp=3072)
    cvt_act<<<(MROWS * DM) / 1024, 256>>>(phln, pa2, DM);
    cvt_wt<<<(FFN * DM) / 1024, 256>>>(ffn_w1, pb2, FFN, DM);
    gemm_mma<1><<<dim3(FFN / BN, MROWS / BM), 256, GSMEM>>>(
        pa2, pb2, pt, ffn_b1, nullptr, FFN, 3 * DM);

    // 10. FFN2 + bias + residual(x1) -> out  (Kp=12288)
    cvt_act<<<(MROWS * FFN) / 1024, 256>>>(pt, pa2, FFN);
    cvt_wt<<<(1024 * FFN) / 1024, 256>>>(ffn_w2, pb2, DM, FFN);
    gemm_mma<2><<<dim3(DM / BN, MROWS / BM), 256, GSMEM>>>(
        pa2, pb2, out, ffn_b2, px1, DM, 3 * FFN);
}

// round 16
// speedup vs baseline: 2.2301x; 1.2352x over previous
#include <cuda_runtime.h>
#include <cuda_bf16.h>
#include <math.h>
#include <stdint.h>

// ---------------------------------------------------------------------------
// Shapes
// ---------------------------------------------------------------------------
#define B_SZ   2
#define SEQ    2048
#define MROWS  4096
#define DM     1024
#define DI     2048
#define CONVD  2176
#define DIP    4256
#define NH     32
#define FFN    4096

// scan chunking
#define NCH    16
#define CHL    128
#define NTASK  (B_SZ * NH * NCH)   // 1024

// GEMM tiling (mma.sync path): 128x128x32 tile, 4-stage pipeline
#define BM     128
#define BN     128
#define BKE    32          // bf16 elems per K iteration (64B per row)
#define ROWB   80          // 64B data + 16B skew -> conflict-free ldmatrix
#define TILEB  (128 * ROWB)        // 10240 per operand-stage
#define NSTG   4
#define GSMEM  (2 * NSTG * TILEB)  // 81920 dynamic smem

// ---------------------------------------------------------------------------
// Scratch (static device globals; no allocation allowed)
// ---------------------------------------------------------------------------
__device__ __align__(256) float g_x0 [MROWS * DM];
__device__ __align__(256) float g_u  [MROWS * DM];
__device__ __align__(256) float g_zx [MROWS * DIP];
__device__ __align__(256) float g_xc [MROWS * CONVD];
__device__ __align__(256) float g_dt [MROWS * NH];
__device__ __align__(256) float g_dA [MROWS * NH];
__device__ __align__(256) float g_ydp[MROWS * DI];
__device__ __align__(256) float g_yn [MROWS * DI];
__device__ __align__(256) float g_x1 [MROWS * DM];
__device__ __align__(256) float g_hln[MROWS * DM];
__device__ __align__(256) float g_t  [MROWS * FFN];
// scan chunk scratch
__device__ __align__(256) float g_cp [MROWS * NH];
__device__ __align__(256) float g_S  [(size_t)NTASK * 4096];
__device__ __align__(256) float g_Hin[(size_t)NTASK * 4096];
// split-bf16 staging
__device__ __align__(256) __nv_bfloat16 g_a2[(size_t)MROWS * 12288];
__device__ __align__(256) __nv_bfloat16 g_b2[(size_t)4352 * 3072];

// ---------------------------------------------------------------------------
// Helpers
// ---------------------------------------------------------------------------
__device__ __forceinline__ uint32_t s2u(const void* p) {
    uint32_t r;
    asm("{ .reg .u64 t; cvta.to.shared.u64 t, %1; cvt.u32.u64 %0, t; }" : "=r"(r) : "l"(p));
    return r;
}
__device__ __forceinline__ void cpa16(uint32_t dst, const void* src) {
    asm volatile("cp.async.cg.shared.global [%0], [%1], 16;" :: "r"(dst), "l"(src));
}
__device__ __forceinline__ void ldsm4(uint32_t* r, uint32_t a) {
    asm volatile("ldmatrix.sync.aligned.m8n8.x4.shared.b16 {%0,%1,%2,%3}, [%4];"
                 : "=r"(r[0]), "=r"(r[1]), "=r"(r[2]), "=r"(r[3]) : "r"(a));
}
__device__ __forceinline__ void mma16816(float* d, const uint32_t* a, const uint32_t* b) {
    asm volatile("mma.sync.aligned.m16n8k16.row.col.f32.bf16.bf16.f32 "
                 "{%0,%1,%2,%3}, {%4,%5,%6,%7}, {%8,%9}, {%0,%1,%2,%3};"
                 : "+f"(d[0]), "+f"(d[1]), "+f"(d[2]), "+f"(d[3])
                 : "r"(a[0]), "r"(a[1]), "r"(a[2]), "r"(a[3]), "r"(b[0]), "r"(b[1]));
}

// ---------------------------------------------------------------------------
// split-bf16 conversion kernels (vectorized: float4 in, bf16x2 out)
// act: [hi | lo | hi] along K' = 3K     wt: [hi | hi | lo], rows >= Nreal zeroed
// ---------------------------------------------------------------------------
__global__ void cvt_act(const float* __restrict__ src, __nv_bfloat16* __restrict__ dst, int K) {
    int idx = (blockIdx.x * blockDim.x + threadIdx.x) * 4;
    int row = idx / K, k = idx - row * K;
    float4 v = *(const float4*)(src + idx);
    __nv_bfloat16 h0 = __float2bfloat16(v.x), h1 = __float2bfloat16(v.y);
    __nv_bfloat16 h2 = __float2bfloat16(v.z), h3 = __float2bfloat16(v.w);
    __nv_bfloat16 l0 = __float2bfloat16(v.x - __bfloat162float(h0));
    __nv_bfloat16 l1 = __float2bfloat16(v.y - __bfloat162float(h1));
    __nv_bfloat16 l2 = __float2bfloat16(v.z - __bfloat162float(h2));
    __nv_bfloat16 l3 = __float2bfloat16(v.w - __bfloat162float(h3));
    size_t b = (size_t)row * 3 * K;
    __nv_bfloat162* p0 = (__nv_bfloat162*)(dst + b + k);
    __nv_bfloat162* p1 = (__nv_bfloat162*)(dst + b + K + k);
    __nv_bfloat162* p2 = (__nv_bfloat162*)(dst + b + 2 * K + k);
    p0[0] = __halves2bfloat162(h0, h1); p0[1] = __halves2bfloat162(h2, h3);
    p1[0] = __halves2bfloat162(l0, l1); p1[1] = __halves2bfloat162(l2, l3);
    p2[0] = __halves2bfloat162(h0, h1); p2[1] = __halves2bfloat162(h2, h3);
}
__global__ void cvt_wt(const float* __restrict__ src, __nv_bfloat16* __restrict__ dst,
                       int Nreal, int K) {
    int idx = (blockIdx.x * blockDim.x + threadIdx.x) * 4;
    int row = idx / K, k = idx - row * K;
    float4 v = make_float4(0.f, 0.f, 0.f, 0.f);
    if (row < Nreal) v = *(const float4*)(src + (size_t)row * K + k);
    __nv_bfloat16 h0 = __float2bfloat16(v.x), h1 = __float2bfloat16(v.y);
    __nv_bfloat16 h2 = __float2bfloat16(v.z), h3 = __float2bfloat16(v.w);
    __nv_bfloat16 l0 = __float2bfloat16(v.x - __bfloat162float(h0));
    __nv_bfloat16 l1 = __float2bfloat16(v.y - __bfloat162float(h1));
    __nv_bfloat16 l2 = __float2bfloat16(v.z - __bfloat162float(h2));
    __nv_bfloat16 l3 = __float2bfloat16(v.w - __bfloat162float(h3));
    size_t b = (size_t)row * 3 * K;
    __nv_bfloat162* p0 = (__nv_bfloat162*)(dst + b + k);
    __nv_bfloat162* p1 = (__nv_bfloat162*)(dst + b + K + k);
    __nv_bfloat162* p2 = (__nv_bfloat162*)(dst + b + 2 * K + k);
    p0[0] = __halves2bfloat162(h0, h1); p0[1] = __halves2bfloat162(h2, h3);
    p1[0] = __halves2bfloat162(h0, h1); p1[1] = __halves2bfloat162(h2, h3);
    p2[0] = __halves2bfloat162(l0, l1); p2[1] = __halves2bfloat162(l2, l3);
}

// ---------------------------------------------------------------------------
// bf16 mma.sync GEMM: C[M,N] = A2[M,Kp] * B2[Npad,Kp]^T, fp32 accumulate
// 4-stage cp.async pipeline, one __syncthreads per K-iteration.
// EPI: 0 none, 1 bias+gelu, 2 bias+residual, 3 residual
// ---------------------------------------------------------------------------
template<int EPI>
__global__ __launch_bounds__(256, 2)
void gemm_mma(const __nv_bfloat16* __restrict__ A2, const __nv_bfloat16* __restrict__ B2,
              float* __restrict__ C, const float* __restrict__ bias,
              const float* __restrict__ R, int N, int Kp) {
    extern __shared__ char dynsm[];
    // A stages: dynsm + st*TILEB ; B stages: dynsm + NSTG*TILEB + st*TILEB
    int tid = threadIdx.x, lane = tid & 31, wid = tid >> 5;
    int row0 = blockIdx.y * BM, col0 = blockIdx.x * BN;
    int wm = (wid & 3) * 32, wn = (wid >> 2) * 64;

    // cp.async: per stage per operand 128 rows x 4 x 16B = 512 chunks; 2/thread
    int crow = tid >> 1;
    int cc0  = (tid & 1) * 2;            // chunks cc0, cc0+1
    size_t KpB = (size_t)Kp * 2;
    const char* gA = (const char*)A2 + (size_t)(row0 + crow) * KpB + cc0 * 16;
    const char* gB = (const char*)B2 + (size_t)(col0 + crow) * KpB + cc0 * 16;
    uint32_t so = crow * ROWB + cc0 * 16;
    uint32_t sa0 = s2u(dynsm) + so;
    uint32_t sb0 = s2u(dynsm) + NSTG * TILEB + so;

    float acc[2][8][4];
#pragma unroll
    for (int i = 0; i < 2; i++)
#pragma unroll
        for (int j = 0; j < 8; j++)
#pragma unroll
            for (int k = 0; k < 4; k++) acc[i][j][k] = 0.f;

    const int NC = Kp / BKE;

    // preload stages 0..2
#pragma unroll
    for (int st = 0; st < NSTG - 1; st++) {
        const char* ga = gA + (size_t)st * 64;
        const char* gb = gB + (size_t)st * 64;
        cpa16(sa0 + st * TILEB, ga);      cpa16(sa0 + st * TILEB + 16, ga + 16);
        cpa16(sb0 + st * TILEB, gb);      cpa16(sb0 + st * TILEB + 16, gb + 16);
        asm volatile("cp.async.commit_group;" ::: "memory");
    }

    // ldmatrix lane address components
    int q = lane >> 3, rr8 = lane & 7;
    int a_row = (q & 1) * 8 + rr8;
    int a_kc  = (q >> 1);
    int b_row = (q >> 1) * 8 + rr8;
    int b_kc  = (q & 1);

    for (int i = 0; i < NC; i++) {
        int buf = i & (NSTG - 1);
        asm volatile("cp.async.wait_group %0;" :: "n"(NSTG - 2) : "memory");
        __syncthreads();

        uint32_t sA = s2u(dynsm) + buf * TILEB;
        uint32_t sB = s2u(dynsm) + NSTG * TILEB + buf * TILEB;
#pragma unroll
        for (int s = 0; s < 2; s++) {
            uint32_t af[2][4], bq[4][4];
#pragma unroll
            for (int mt = 0; mt < 2; mt++)
                ldsm4(af[mt], sA + (wm + mt * 16 + a_row) * ROWB + (s * 2 + a_kc) * 16);
#pragma unroll
            for (int pt = 0; pt < 4; pt++)
                ldsm4(bq[pt], sB + (wn + pt * 16 + b_row) * ROWB + (s * 2 + b_kc) * 16);
#pragma unroll
            for (int mt = 0; mt < 2; mt++)
#pragma unroll
                for (int pt = 0; pt < 4; pt++) {
                    mma16816(acc[mt][pt * 2 + 0], af[mt], &bq[pt][0]);
                    mma16816(acc[mt][pt * 2 + 1], af[mt], &bq[pt][2]);
                }
        }

        int jn = i + NSTG - 1;
        if (jn < NC) {
            int nb = jn & (NSTG - 1);
            const char* ga = gA + (size_t)jn * 64;
            const char* gb = gB + (size_t)jn * 64;
            cpa16(sa0 + nb * TILEB, ga);      cpa16(sa0 + nb * TILEB + 16, ga + 16);
            cpa16(sb0 + nb * TILEB, gb);      cpa16(sb0 + nb * TILEB + 16, gb + 16);
        }
        asm volatile("cp.async.commit_group;" ::: "memory");
    }

    // epilogue
    int g = lane >> 2, t4 = lane & 3;
#pragma unroll
    for (int mt = 0; mt < 2; mt++) {
#pragma unroll
        for (int nt = 0; nt < 8; nt++) {
            int cc = col0 + wn + nt * 8 + t4 * 2;
            if (cc >= N) continue;
            int r1 = row0 + wm + mt * 16 + g;
            int r2 = r1 + 8;
            float v[4] = {acc[mt][nt][0], acc[mt][nt][1], acc[mt][nt][2], acc[mt][nt][3]};
            if (EPI == 1 || EPI == 2) {
                float b0 = bias[cc], b1 = bias[cc + 1];
                v[0] += b0; v[1] += b1; v[2] += b0; v[3] += b1;
            }
            if (EPI == 1) {
#pragma unroll
                for (int e = 0; e < 4; e++)
                    v[e] = 0.5f * v[e] * (1.f + erff(v[e] * 0.70710678118654752f));
            }
            if (EPI == 2 || EPI == 3) {
                v[0] += R[(size_t)r1 * N + cc]; v[1] += R[(size_t)r1 * N + cc + 1];
                v[2] += R[(size_t)r2 * N + cc]; v[3] += R[(size_t)r2 * N + cc + 1];
            }
            *(float2*)&C[(size_t)r1 * N + cc] = make_float2(v[0], v[1]);
            *(float2*)&C[(size_t)r2 * N + cc] = make_float2(v[2], v[3]);
        }
    }
}

// ---------------------------------------------------------------------------
// Block reduce (256 threads) of two values
// ---------------------------------------------------------------------------
__device__ __forceinline__ float2 block_reduce2(float a, float b) {
    __shared__ float sa[8], sb_[8];
    int lane = threadIdx.x & 31, w = threadIdx.x >> 5;
#pragma unroll
    for (int o = 16; o; o >>= 1) {
        a += __shfl_xor_sync(0xffffffffu, a, o);
        b += __shfl_xor_sync(0xffffffffu, b, o);
    }
    __syncthreads();
    if (lane == 0) { sa[w] = a; sb_[w] = b; }
    __syncthreads();
    float ta = 0.f, tb = 0.f;
#pragma unroll
    for (int i = 0; i < 8; i++) { ta += sa[i]; tb += sb_[i]; }
    return make_float2(ta, tb);
}

// ---------------------------------------------------------------------------
// LN0 -> LN1 fused
// ---------------------------------------------------------------------------
__global__ void ln01_kernel(const float* __restrict__ x,
                            const float* __restrict__ w0, const float* __restrict__ b0,
                            const float* __restrict__ w1, const float* __restrict__ b1) {
    int row = blockIdx.x, t = threadIdx.x;
    float4 v = *(const float4*)(x + (size_t)row * DM + t * 4);
    float s = v.x + v.y + v.z + v.w;
    float ss = v.x*v.x + v.y*v.y + v.z*v.z + v.w*v.w;
    float2 r0 = block_reduce2(s, ss);
    float mean = r0.x * (1.f / DM);
    float var = r0.y * (1.f / DM) - mean * mean;
    float rs = rsqrtf(var + 1e-5f);
    int c = t * 4;
    float y0 = (v.x - mean) * rs * w0[c+0] + b0[c+0];
    float y1 = (v.y - mean) * rs * w0[c+1] + b0[c+1];
    float y2 = (v.z - mean) * rs * w0[c+2] + b0[c+2];
    float y3 = (v.w - mean) * rs * w0[c+3] + b0[c+3];
    *(float4*)(g_x0 + (size_t)row * DM + c) = make_float4(y0, y1, y2, y3);
    s = y0 + y1 + y2 + y3;
    ss = y0*y0 + y1*y1 + y2*y2 + y3*y3;
    float2 r1 = block_reduce2(s, ss);
    mean = r1.x * (1.f / DM);
    var = r1.y * (1.f / DM) - mean * mean;
    rs = rsqrtf(var + 1e-5f);
    float u0 = (y0 - mean) * rs * w1[c+0] + b1[c+0];
    float u1 = (y1 - mean) * rs * w1[c+1] + b1[c+1];
    float u2 = (y2 - mean) * rs * w1[c+2] + b1[c+2];
    float u3 = (y3 - mean) * rs * w1[c+3] + b1[c+3];
    *(float4*)(g_u + (size_t)row * DM + c) = make_float4(u0, u1, u2, u3);
}

__global__ void ln2_kernel(const float* __restrict__ w, const float* __restrict__ b) {
    int row = blockIdx.x, t = threadIdx.x;
    float4 v = *(const float4*)(g_x1 + (size_t)row * DM + t * 4);
    float s = v.x + v.y + v.z + v.w;
    float ss = v.x*v.x + v.y*v.y + v.z*v.z + v.w*v.w;
    float2 r0 = block_reduce2(s, ss);
    float mean = r0.x * (1.f / DM);
    float var = r0.y * (1.f / DM) - mean * mean;
    float rs = rsqrtf(var + 1e-5f);
    int c = t * 4;
    float4 o;
    o.x = (v.x - mean) * rs * w[c+0] + b[c+0];
    o.y = (v.y - mean) * rs * w[c+1] + b[c+1];
    o.z = (v.z - mean) * rs * w[c+2] + b[c+2];
    o.w = (v.w - mean) * rs * w[c+3] + b[c+3];
    *(float4*)(g_hln + (size_t)row * DM + c) = o;
}

// ---------------------------------------------------------------------------
// Causal depthwise conv (k=4) + silu
// ---------------------------------------------------------------------------
__global__ void conv_silu_kernel(const float* __restrict__ cw, const float* __restrict__ cb) {
    int c = blockIdx.x * blockDim.x + threadIdx.x;
    if (c >= CONVD) return;
    int r = blockIdx.y;
    int b = r >> 11, l = r & (SEQ - 1);
    float w0 = cw[c*4+0], w1 = cw[c*4+1], w2 = cw[c*4+2], w3 = cw[c*4+3];
    const float* base = g_zx + (size_t)(b * SEQ) * DIP + DI + c;
    float acc = cb[c];
    if (l >= 3) acc = fmaf(w0, base[(size_t)(l-3) * DIP], acc);
    if (l >= 2) acc = fmaf(w1, base[(size_t)(l-2) * DIP], acc);
    if (l >= 1) acc = fmaf(w2, base[(size_t)(l-1) * DIP], acc);
    acc = fmaf(w3, base[(size_t)l * DIP], acc);
    g_xc[(size_t)r * CONVD + c] = acc / (1.f + expf(-acc));
}

__global__ void dt_kernel(const float* __restrict__ dt_bias, const float* __restrict__ A_log) {
    int i = blockIdx.x * blockDim.x + threadIdx.x;
    int r = i >> 5, hh = i & 31;
    float raw = g_zx[(size_t)r * DIP + (DI + CONVD) + hh];
    float v = raw + dt_bias[hh];
    float sp = (v > 20.f) ? v : log1pf(expf(v));
    g_dt[i] = sp;
    g_dA[i] = expf(-expf(A_log[hh]) * sp);
}

// ---------------------------------------------------------------------------
// Chunked selective scan
// ---------------------------------------------------------------------------
__global__ __launch_bounds__(512, 1)
void scan_ph1(const float* __restrict__ Dp) {
    int t = blockIdx.x;
    int c = t & (NCH - 1);
    int bh = t >> 4;
    int b = bh >> 5, h = bh & 31;
    int tid = threadIdx.x;
    int p = tid >> 3, sub = tid & 7, n0 = sub << 3;
    int l0 = c * CHL;

    __shared__ __align__(16) float sx[2][64];
    __shared__ __align__(16) float sB[2][64];
    __shared__ __align__(16) float sC[2][64];
    __shared__ float sdt[2][2];

    float hs[8];
#pragma unroll
    for (int i = 0; i < 8; i++) hs[i] = 0.f;
    float Dv = Dp[h];
    float cp = 1.f;

    const float* xcb = g_xc + (size_t)(b * SEQ) * CONVD;
    float* yb = g_ydp + (size_t)(b * SEQ) * DI;

    for (int ll = 0; ll < CHL; ll++) {
        int l = l0 + ll;
        int buf = ll & 1;
        const float* xr = xcb + (size_t)l * CONVD;
        int ri = (b * SEQ + l) * NH + h;
        if (tid < 64)        sx[buf][tid]       = xr[h * 64 + tid];
        else if (tid < 128)  sB[buf][tid - 64]  = xr[2048 + (tid - 64)];
        else if (tid < 192)  sC[buf][tid - 128] = xr[2112 + (tid - 128)];
        else if (tid == 192) {
            sdt[buf][0] = g_dt[ri];
            sdt[buf][1] = g_dA[ri];
        }
        __syncthreads();

        float dtv = sdt[buf][0], dAv = sdt[buf][1];
        cp *= dAv;
        if (tid == 0) g_cp[ri] = cp;
        float xv = sx[buf][p];
        float dtx = dtv * xv;
        float4 Bv0 = *(const float4*)&sB[buf][n0];
        float4 Bv1 = *(const float4*)&sB[buf][n0 + 4];
        float4 Cv0 = *(const float4*)&sC[buf][n0];
        float4 Cv1 = *(const float4*)&sC[buf][n0 + 4];

        float part;
        hs[0] = fmaf(hs[0], dAv, dtx * Bv0.x); part  = hs[0] * Cv0.x;
        hs[1] = fmaf(hs[1], dAv, dtx * Bv0.y); part += hs[1] * Cv0.y;
        hs[2] = fmaf(hs[2], dAv, dtx * Bv0.z); part += hs[2] * Cv0.z;
        hs[3] = fmaf(hs[3], dAv, dtx * Bv0.w); part += hs[3] * Cv0.w;
        hs[4] = fmaf(hs[4], dAv, dtx * Bv1.x); part += hs[4] * Cv1.x;
        hs[5] = fmaf(hs[5], dAv, dtx * Bv1.y); part += hs[5] * Cv1.y;
        hs[6] = fmaf(hs[6], dAv, dtx * Bv1.z); part += hs[6] * Cv1.z;
        hs[7] = fmaf(hs[7], dAv, dtx * Bv1.w); part += hs[7] * Cv1.w;

        part += __shfl_xor_sync(0xffffffffu, part, 1);
        part += __shfl_xor_sync(0xffffffffu, part, 2);
        part += __shfl_xor_sync(0xffffffffu, part, 4);

        if (sub == 0)
            yb[(size_t)l * DI + h * 64 + p] = fmaf(Dv, xv, part);
    }

    float* Sp = g_S + (size_t)t * 4096 + p * 64 + n0;
    *(float4*)(Sp + 0) = make_float4(hs[0], hs[1], hs[2], hs[3]);
    *(float4*)(Sp + 4) = make_float4(hs[4], hs[5], hs[6], hs[7]);
}

__global__ __launch_bounds__(512, 1)
void scan_ph2() {
    int bh = blockIdx.x;
    int b = bh >> 5, h = bh & 31;
    int e = threadIdx.x * 8;
    float H[8];
#pragma unroll
    for (int i = 0; i < 8; i++) H[i] = 0.f;

    for (int c = 0; c < NCH; c++) {
        size_t t = (size_t)(bh * NCH + c);
        float* dst = g_Hin + t * 4096 + e;
        *(float4*)(dst + 0) = make_float4(H[0], H[1], H[2], H[3]);
        *(float4*)(dst + 4) = make_float4(H[4], H[5], H[6], H[7]);
        float cpT = g_cp[(b * SEQ + c * CHL + CHL - 1) * NH + h];
        const float* Sp = g_S + t * 4096 + e;
        float4 s0 = *(const float4*)(Sp + 0);
        float4 s1 = *(const float4*)(Sp + 4);
        H[0] = fmaf(cpT, H[0], s0.x); H[1] = fmaf(cpT, H[1], s0.y);
        H[2] = fmaf(cpT, H[2], s0.z); H[3] = fmaf(cpT, H[3], s0.w);
        H[4] = fmaf(cpT, H[4], s1.x); H[5] = fmaf(cpT, H[5], s1.y);
        H[6] = fmaf(cpT, H[6], s1.z); H[7] = fmaf(cpT, H[7], s1.w);
    }
}

__global__ __launch_bounds__(512, 1)
void scan_ph3() {
    int t = blockIdx.x;
    int c = t & (NCH - 1);
    int bh = t >> 4;
    int b = bh >> 5, h = bh & 31;
    int tid = threadIdx.x;
    int p = tid >> 3, sub = tid & 7, n0 = sub << 3;
    int l0 = c * CHL;

    __shared__ __align__(16) float sH[4096];
    {
        const float* src = g_Hin + (size_t)t * 4096 + tid * 8;
        float4 a = *(const float4*)(src + 0);
        float4 bb = *(const float4*)(src + 4);
        *(float4*)&sH[tid * 8 + 0] = a;
        *(float4*)&sH[tid * 8 + 4] = bb;
    }
    __syncthreads();

    float H[8];
#pragma unroll
    for (int i = 0; i < 8; i++) H[i] = sH[p * 64 + n0 + i];

    const float* xcb = g_xc + (size_t)(b * SEQ) * CONVD;
    float* yb = g_ydp + (size_t)(b * SEQ) * DI;

    for (int ll = 0; ll < CHL; ll++) {
        int l = l0 + ll;
        const float* xr = xcb + (size_t)l * CONVD;
        float cp = g_cp[(b * SEQ + l) * NH + h];
        float4 Cv0 = *(const float4*)(xr + 2112 + n0);
        float4 Cv1 = *(const float4*)(xr + 2112 + n0 + 4);
        float part = H[0] * Cv0.x + H[1] * Cv0.y + H[2] * Cv0.z + H[3] * Cv0.w
                   + H[4] * Cv1.x + H[5] * Cv1.y + H[6] * Cv1.z + H[7] * Cv1.w;
        part += __shfl_xor_sync(0xffffffffu, part, 1);
        part += __shfl_xor_sync(0xffffffffu, part, 2);
        part += __shfl_xor_sync(0xffffffffu, part, 4);
        if (sub == 0) {
            size_t yi = (size_t)l * DI + h * 64 + p;
            yb[yi] += cp * part;
        }
    }
}

// ---------------------------------------------------------------------------
// Gate + RMSNorm
// ---------------------------------------------------------------------------
__global__ void gate_rms_kernel(const float* __restrict__ norm_w) {
    int row = blockIdx.x, t = threadIdx.x;
    const float* zr = g_zx + (size_t)row * DIP;
    const float* yr = g_ydp + (size_t)row * DI;
    int c0 = t * 8;
    float g[8];
    float ss = 0.f;
#pragma unroll
    for (int k = 0; k < 2; k++) {
        float4 zv = *(const float4*)(zr + c0 + k * 4);
        float4 yv = *(const float4*)(yr + c0 + k * 4);
        float g0 = yv.x * (zv.x / (1.f + expf(-zv.x)));
        float g1 = yv.y * (zv.y / (1.f + expf(-zv.y)));
        float g2 = yv.z * (zv.z / (1.f + expf(-zv.z)));
        float g3 = yv.w * (zv.w / (1.f + expf(-zv.w)));
        g[k*4+0] = g0; g[k*4+1] = g1; g[k*4+2] = g2; g[k*4+3] = g3;
        ss += g0*g0 + g1*g1 + g2*g2 + g3*g3;
    }
    float2 r = block_reduce2(ss, 0.f);
    float rs = rsqrtf(r.x * (1.f / DI) + 1e-5f);
    float* outr = g_yn + (size_t)row * DI;
#pragma unroll
    for (int k = 0; k < 2; k++) {
        float4 o;
        o.x = g[k*4+0] * rs * norm_w[c0 + k*4+0];
        o.y = g[k*4+1] * rs * norm_w[c0 + k*4+1];
        o.z = g[k*4+2] * rs * norm_w[c0 + k*4+2];
        o.w = g[k*4+3] * rs * norm_w[c0 + k*4+3];
        *(float4*)(outr + c0 + k*4) = o;
    }
}

// ---------------------------------------------------------------------------
// Host launcher
// ---------------------------------------------------------------------------
extern "C" void kernel_launch(void* const* d_in, const int* in_sizes, int n_in,
                              void* d_out, int out_size) {
    const float* x         = (const float*)d_in[0];
    const float* ln0_w     = (const float*)d_in[1];
    const float* ln0_b     = (const float*)d_in[2];
    const float* ln1_w     = (const float*)d_in[3];
    const float* ln1_b     = (const float*)d_in[4];
    const float* ln2_w     = (const float*)d_in[5];
    const float* ln2_b     = (const float*)d_in[6];
    const float* in_proj_w = (const float*)d_in[7];
    const float* conv_w    = (const float*)d_in[8];
    const float* conv_b    = (const float*)d_in[9];
    const float* dt_bias   = (const float*)d_in[10];
    const float* A_log     = (const float*)d_in[11];
    const float* D_param   = (const float*)d_in[12];
    const float* norm_w    = (const float*)d_in[13];
    const float* out_proj_w= (const float*)d_in[14];
    const float* ffn_w1    = (const float*)d_in[15];
    const float* ffn_b1    = (const float*)d_in[16];
    const float* ffn_w2    = (const float*)d_in[17];
    const float* ffn_b2    = (const float*)d_in[18];
    float* out = (float*)d_out;

    float *pu, *px0, *pzx, *pyn, *px1, *phln, *pt;
    __nv_bfloat16 *pa2, *pb2;
    cudaGetSymbolAddress((void**)&pu,   g_u);
    cudaGetSymbolAddress((void**)&px0,  g_x0);
    cudaGetSymbolAddress((void**)&pzx,  g_zx);
    cudaGetSymbolAddress((void**)&pyn,  g_yn);
    cudaGetSymbolAddress((void**)&px1,  g_x1);
    cudaGetSymbolAddress((void**)&phln, g_hln);
    cudaGetSymbolAddress((void**)&pt,   g_t);
    cudaGetSymbolAddress((void**)&pa2,  g_a2);
    cudaGetSymbolAddress((void**)&pb2,  g_b2);

    cudaFuncSetAttribute(gemm_mma<0>, cudaFuncAttributeMaxDynamicSharedMemorySize, GSMEM);
    cudaFuncSetAttribute(gemm_mma<1>, cudaFuncAttributeMaxDynamicSharedMemorySize, GSMEM);
    cudaFuncSetAttribute(gemm_mma<2>, cudaFuncAttributeMaxDynamicSharedMemorySize, GSMEM);
    cudaFuncSetAttribute(gemm_mma<3>, cudaFuncAttributeMaxDynamicSharedMemorySize, GSMEM);

    // 1. LN0 + LN1
    ln01_kernel<<<MROWS, 256>>>(x, ln0_w, ln0_b, ln1_w, ln1_b);

    // 2. in_proj: [4096,1024] x [4256,1024]^T  (split-bf16, Npad=4352, Kp=3072)
    cvt_act<<<(MROWS * DM) / 1024, 256>>>(pu, pa2, DM);
    cvt_wt<<<(4352 * DM) / 1024, 256>>>(in_proj_w, pb2, DIP, DM);
    gemm_mma<0><<<dim3(4352 / BN, MROWS / BM), 256, GSMEM>>>(
        pa2, pb2, pzx, nullptr, nullptr, DIP, 3 * DM);

    // 3-6. conv, dt, chunked scan, gate
    conv_silu_kernel<<<dim3((CONVD + 255) / 256, MROWS), 256>>>(conv_w, conv_b);
    dt_kernel<<<(MROWS * NH) / 256, 256>>>(dt_bias, A_log);
    scan_ph1<<<NTASK, 512>>>(D_param);
    scan_ph2<<<B_SZ * NH, 512>>>();
    scan_ph3<<<NTASK, 512>>>();
    gate_rms_kernel<<<MROWS, 256>>>(norm_w);

    // 7. out_proj + residual(x0) -> x1  (Kp=6144)
    cvt_act<<<(MROWS * DI) / 1024, 256>>>(pyn, pa2, DI);
    cvt_wt<<<(1024 * DI) / 1024, 256>>>(out_proj_w, pb2, DM, DI);
    gemm_mma<3><<<dim3(DM / BN, MROWS / BM), 256, GSMEM>>>(
        pa2, pb2, px1, nullptr, px0, DM, 3 * DI);

    // 8. LN2
    ln2_kernel<<<MROWS, 256>>>(ln2_w, ln2_b);

    // 9. FFN1 + bias + gelu  (Kp=3072)
    cvt_act<<<(MROWS * DM) / 1024, 256>>>(phln, pa2, DM);
    cvt_wt<<<(FFN * DM) / 1024, 256>>>(ffn_w1, pb2, FFN, DM);
    gemm_mma<1><<<dim3(FFN / BN, MROWS / BM), 256, GSMEM>>>(
        pa2, pb2, pt, ffn_b1, nullptr, FFN, 3 * DM);

    // 10. FFN2 + bias + residual(x1) -> out  (Kp=12288)
    cvt_act<<<(MROWS * FFN) / 1024, 256>>>(pt, pa2, FFN);
    cvt_wt<<<(1024 * FFN) / 1024, 256>>>(ffn_w2, pb2, DM, FFN);
    gemm_mma<2><<<dim3(DM / BN, MROWS / BM), 256, GSMEM>>>(
        pa2, pb2, out, ffn_b2, px1, DM, 3 * FFN);
}

// round 17
// speedup vs baseline: 2.8371x; 1.2722x over previous
#include <cuda_runtime.h>
#include <cuda_fp16.h>
#include <math.h>
#include <stdint.h>

// ---------------------------------------------------------------------------
// Shapes
// ---------------------------------------------------------------------------
#define B_SZ   2
#define SEQ    2048
#define MROWS  4096
#define DM     1024
#define DI     2048
#define CONVD  2176
#define DIP    4256
#define NH     32
#define FFN    4096

// scan chunking
#define NCH    16
#define CHL    128
#define NTASK  (B_SZ * NH * NCH)   // 1024

// GEMM tiling: 128x128x32 tile, 4-stage cp.async pipeline (R16-proven)
#define BM     128
#define BN     128
#define BKE    32          // fp16 elems per K iteration (64B per row)
#define ROWB   80          // 64B data + 16B skew -> conflict-free ldmatrix
#define TILEB  (128 * ROWB)        // 10240 per operand-stage
#define NSTG   4
#define GSMEM  (2 * NSTG * TILEB)  // 81920 dynamic smem

// ---------------------------------------------------------------------------
// Scratch (static device globals; no allocation allowed)
// ---------------------------------------------------------------------------
__device__ __align__(256) float g_x0 [MROWS * DM];
__device__ __align__(256) float g_zx [MROWS * DIP];
__device__ __align__(256) float g_xc [MROWS * CONVD];
__device__ __align__(256) float g_dt [MROWS * NH];
__device__ __align__(256) float g_dA [MROWS * NH];
__device__ __align__(256) float g_ydp[MROWS * DI];
__device__ __align__(256) float g_x1 [MROWS * DM];
// scan chunk scratch
__device__ __align__(256) float g_cp [MROWS * NH];
__device__ __align__(256) float g_S  [(size_t)NTASK * 4096];
__device__ __align__(256) float g_Hin[(size_t)NTASK * 4096];
// fp16 split staging:
//   g_a2[0 .. MROWS*4096)          : activation split region (stride 2048 or 4096)
//   g_a2[MROWS*4096 .. MROWS*12288): gelu split region (stride 8192)
__device__ __align__(256) __half g_a2[(size_t)MROWS * 12288];
__device__ __align__(256) __half g_b2[(size_t)4352 * 2048];

// ---------------------------------------------------------------------------
// Helpers
// ---------------------------------------------------------------------------
__device__ __forceinline__ uint32_t s2u(const void* p) {
    uint32_t r;
    asm("{ .reg .u64 t; cvta.to.shared.u64 t, %1; cvt.u32.u64 %0, t; }" : "=r"(r) : "l"(p));
    return r;
}
__device__ __forceinline__ void cpa16(uint32_t dst, const void* src) {
    asm volatile("cp.async.cg.shared.global [%0], [%1], 16;" :: "r"(dst), "l"(src));
}
__device__ __forceinline__ void ldsm4(uint32_t* r, uint32_t a) {
    asm volatile("ldmatrix.sync.aligned.m8n8.x4.shared.b16 {%0,%1,%2,%3}, [%4];"
                 : "=r"(r[0]), "=r"(r[1]), "=r"(r[2]), "=r"(r[3]) : "r"(a));
}
__device__ __forceinline__ void mma16816(float* d, const uint32_t* a, const uint32_t* b) {
    asm volatile("mma.sync.aligned.m16n8k16.row.col.f32.f16.f16.f32 "
                 "{%0,%1,%2,%3}, {%4,%5,%6,%7}, {%8,%9}, {%0,%1,%2,%3};"
                 : "+f"(d[0]), "+f"(d[1]), "+f"(d[2]), "+f"(d[3])
                 : "r"(a[0]), "r"(a[1]), "r"(a[2]), "r"(a[3]), "r"(b[0]), "r"(b[1]));
}
__device__ __forceinline__ __half2 mk2(float a, float b) {
    return __halves2half2(__float2half_rn(a), __float2half_rn(b));
}
// split v into fp16 hi+lo; hi returned via h, lo via l
__device__ __forceinline__ void fsplit(float v, __half& h, __half& l) {
    h = __float2half_rn(v);
    l = __float2half_rn(v - __half2float(h));
}

// ---------------------------------------------------------------------------
// Weight conversion: B = [hi | hi] along Kp = 2K; rows >= Nreal zeroed
// ---------------------------------------------------------------------------
__global__ void cvt_wt(const float* __restrict__ src, __half* __restrict__ dst,
                       int Nreal, int K) {
    int idx = (blockIdx.x * blockDim.x + threadIdx.x) * 4;   // over Npad*K
    int row = idx / K, k = idx - row * K;
    float4 v = make_float4(0.f, 0.f, 0.f, 0.f);
    if (row < Nreal) v = *(const float4*)(src + (size_t)row * K + k);
    __half2 h01 = mk2(v.x, v.y), h23 = mk2(v.z, v.w);
    size_t b = (size_t)row * 2 * K;
    __half2* p0 = (__half2*)(dst + b + k);
    __half2* p1 = (__half2*)(dst + b + K + k);
    p0[0] = h01; p0[1] = h23;
    p1[0] = h01; p1[1] = h23;
}

// ---------------------------------------------------------------------------
// fp16 mma.sync GEMM: C[M,N] = A2[M,Kp] * B2[Npad,Kp]^T, fp32 accumulate
// 4-stage cp.async pipeline, one __syncthreads per K-iteration.
// EPI: 0 none, 1 bias+gelu -> fp16 split into GE (stride 8192, [hi|lo]),
//      2 bias+residual, 3 residual
// ---------------------------------------------------------------------------
template<int EPI>
__global__ __launch_bounds__(256, 2)
void gemm_mma(const __half* __restrict__ A2, const __half* __restrict__ B2,
              float* __restrict__ C, const float* __restrict__ bias,
              const float* __restrict__ R, __half* __restrict__ GE, int N, int Kp) {
    extern __shared__ char dynsm[];
    int tid = threadIdx.x, lane = tid & 31, wid = tid >> 5;
    int row0 = blockIdx.y * BM, col0 = blockIdx.x * BN;
    int wm = (wid & 3) * 32, wn = (wid >> 2) * 64;

    int crow = tid >> 1;
    int cc0  = (tid & 1) * 2;
    size_t KpB = (size_t)Kp * 2;
    const char* gA = (const char*)A2 + (size_t)(row0 + crow) * KpB + cc0 * 16;
    const char* gB = (const char*)B2 + (size_t)(col0 + crow) * KpB + cc0 * 16;
    uint32_t so = crow * ROWB + cc0 * 16;
    uint32_t sa0 = s2u(dynsm) + so;
    uint32_t sb0 = s2u(dynsm) + NSTG * TILEB + so;

    float acc[2][8][4];
#pragma unroll
    for (int i = 0; i < 2; i++)
#pragma unroll
        for (int j = 0; j < 8; j++)
#pragma unroll
            for (int k = 0; k < 4; k++) acc[i][j][k] = 0.f;

    const int NC = Kp / BKE;

#pragma unroll
    for (int st = 0; st < NSTG - 1; st++) {
        const char* ga = gA + (size_t)st * 64;
        const char* gb = gB + (size_t)st * 64;
        cpa16(sa0 + st * TILEB, ga);      cpa16(sa0 + st * TILEB + 16, ga + 16);
        cpa16(sb0 + st * TILEB, gb);      cpa16(sb0 + st * TILEB + 16, gb + 16);
        asm volatile("cp.async.commit_group;" ::: "memory");
    }

    int q = lane >> 3, rr8 = lane & 7;
    int a_row = (q & 1) * 8 + rr8;
    int a_kc  = (q >> 1);
    int b_row = (q >> 1) * 8 + rr8;
    int b_kc  = (q & 1);

    for (int i = 0; i < NC; i++) {
        int buf = i & (NSTG - 1);
        asm volatile("cp.async.wait_group %0;" :: "n"(NSTG - 2) : "memory");
        __syncthreads();

        uint32_t sA = s2u(dynsm) + buf * TILEB;
        uint32_t sB = s2u(dynsm) + NSTG * TILEB + buf * TILEB;
#pragma unroll
        for (int s = 0; s < 2; s++) {
            uint32_t af[2][4], bq[4][4];
#pragma unroll
            for (int mt = 0; mt < 2; mt++)
                ldsm4(af[mt], sA + (wm + mt * 16 + a_row) * ROWB + (s * 2 + a_kc) * 16);
#pragma unroll
            for (int pt = 0; pt < 4; pt++)
                ldsm4(bq[pt], sB + (wn + pt * 16 + b_row) * ROWB + (s * 2 + b_kc) * 16);
#pragma unroll
            for (int mt = 0; mt < 2; mt++)
#pragma unroll
                for (int pt = 0; pt < 4; pt++) {
                    mma16816(acc[mt][pt * 2 + 0], af[mt], &bq[pt][0]);
                    mma16816(acc[mt][pt * 2 + 1], af[mt], &bq[pt][2]);
                }
        }

        int jn = i + NSTG - 1;
        if (jn < NC) {
            int nb = jn & (NSTG - 1);
            const char* ga = gA + (size_t)jn * 64;
            const char* gb = gB + (size_t)jn * 64;
            cpa16(sa0 + nb * TILEB, ga);      cpa16(sa0 + nb * TILEB + 16, ga + 16);
            cpa16(sb0 + nb * TILEB, gb);      cpa16(sb0 + nb * TILEB + 16, gb + 16);
        }
        asm volatile("cp.async.commit_group;" ::: "memory");
    }

    // epilogue
    int g = lane >> 2, t4 = lane & 3;
#pragma unroll
    for (int mt = 0; mt < 2; mt++) {
#pragma unroll
        for (int nt = 0; nt < 8; nt++) {
            int cc = col0 + wn + nt * 8 + t4 * 2;
            if (cc >= N) continue;
            int r1 = row0 + wm + mt * 16 + g;
            int r2 = r1 + 8;
            float v[4] = {acc[mt][nt][0], acc[mt][nt][1], acc[mt][nt][2], acc[mt][nt][3]};
            if (EPI == 1 || EPI == 2) {
                float b0 = bias[cc], b1 = bias[cc + 1];
                v[0] += b0; v[1] += b1; v[2] += b0; v[3] += b1;
            }
            if (EPI == 1) {
                // bias + exact gelu, then fp16 [hi|lo] split into GE (stride 8192)
#pragma unroll
                for (int e = 0; e < 4; e++)
                    v[e] = 0.5f * v[e] * (1.f + erff(v[e] * 0.70710678118654752f));
                __half h0, h1, h2, h3, l0, l1, l2, l3;
                fsplit(v[0], h0, l0); fsplit(v[1], h1, l1);
                fsplit(v[2], h2, l2); fsplit(v[3], h3, l3);
                *(__half2*)(GE + (size_t)r1 * 8192 + cc)        = __halves2half2(h0, h1);
                *(__half2*)(GE + (size_t)r1 * 8192 + 4096 + cc) = __halves2half2(l0, l1);
                *(__half2*)(GE + (size_t)r2 * 8192 + cc)        = __halves2half2(h2, h3);
                *(__half2*)(GE + (size_t)r2 * 8192 + 4096 + cc) = __halves2half2(l2, l3);
            } else {
                if (EPI == 2 || EPI == 3) {
                    v[0] += R[(size_t)r1 * N + cc]; v[1] += R[(size_t)r1 * N + cc + 1];
                    v[2] += R[(size_t)r2 * N + cc]; v[3] += R[(size_t)r2 * N + cc + 1];
                }
                *(float2*)&C[(size_t)r1 * N + cc] = make_float2(v[0], v[1]);
                *(float2*)&C[(size_t)r2 * N + cc] = make_float2(v[2], v[3]);
            }
        }
    }
}

// ---------------------------------------------------------------------------
// Block reduce (256 threads) of two values
// ---------------------------------------------------------------------------
__device__ __forceinline__ float2 block_reduce2(float a, float b) {
    __shared__ float sa[8], sb_[8];
    int lane = threadIdx.x & 31, w = threadIdx.x >> 5;
#pragma unroll
    for (int o = 16; o; o >>= 1) {
        a += __shfl_xor_sync(0xffffffffu, a, o);
        b += __shfl_xor_sync(0xffffffffu, b, o);
    }
    __syncthreads();
    if (lane == 0) { sa[w] = a; sb_[w] = b; }
    __syncthreads();
    float ta = 0.f, tb = 0.f;
#pragma unroll
    for (int i = 0; i < 8; i++) { ta += sa[i]; tb += sb_[i]; }
    return make_float2(ta, tb);
}

// ---------------------------------------------------------------------------
// LN0 -> LN1 fused; writes x0 (fp32 residual) and u fp16 split (stride 2048)
// ---------------------------------------------------------------------------
__global__ void ln01_kernel(const float* __restrict__ x,
                            const float* __restrict__ w0, const float* __restrict__ b0,
                            const float* __restrict__ w1, const float* __restrict__ b1) {
    int row = blockIdx.x, t = threadIdx.x;
    float4 v = *(const float4*)(x + (size_t)row * DM + t * 4);
    float s = v.x + v.y + v.z + v.w;
    float ss = v.x*v.x + v.y*v.y + v.z*v.z + v.w*v.w;
    float2 r0 = block_reduce2(s, ss);
    float mean = r0.x * (1.f / DM);
    float var = r0.y * (1.f / DM) - mean * mean;
    float rs = rsqrtf(var + 1e-5f);
    int c = t * 4;
    float y0 = (v.x - mean) * rs * w0[c+0] + b0[c+0];
    float y1 = (v.y - mean) * rs * w0[c+1] + b0[c+1];
    float y2 = (v.z - mean) * rs * w0[c+2] + b0[c+2];
    float y3 = (v.w - mean) * rs * w0[c+3] + b0[c+3];
    *(float4*)(g_x0 + (size_t)row * DM + c) = make_float4(y0, y1, y2, y3);
    s = y0 + y1 + y2 + y3;
    ss = y0*y0 + y1*y1 + y2*y2 + y3*y3;
    float2 r1 = block_reduce2(s, ss);
    mean = r1.x * (1.f / DM);
    var = r1.y * (1.f / DM) - mean * mean;
    rs = rsqrtf(var + 1e-5f);
    float u0 = (y0 - mean) * rs * w1[c+0] + b1[c+0];
    float u1 = (y1 - mean) * rs * w1[c+1] + b1[c+1];
    float u2 = (y2 - mean) * rs * w1[c+2] + b1[c+2];
    float u3 = (y3 - mean) * rs * w1[c+3] + b1[c+3];
    __half h0, h1, h2, h3, l0, l1, l2, l3;
    fsplit(u0, h0, l0); fsplit(u1, h1, l1); fsplit(u2, h2, l2); fsplit(u3, h3, l3);
    __half* a2 = g_a2 + (size_t)row * 2048;
    *(__half2*)(a2 + c)            = __halves2half2(h0, h1);
    *(__half2*)(a2 + c + 2)        = __halves2half2(h2, h3);
    *(__half2*)(a2 + 1024 + c)     = __halves2half2(l0, l1);
    *(__half2*)(a2 + 1024 + c + 2) = __halves2half2(l2, l3);
}

// LN2: reads g_x1, writes hln fp16 split (stride 2048)
__global__ void ln2_kernel(const float* __restrict__ w, const float* __restrict__ b) {
    int row = blockIdx.x, t = threadIdx.x;
    float4 v = *(const float4*)(g_x1 + (size_t)row * DM + t * 4);
    float s = v.x + v.y + v.z + v.w;
    float ss = v.x*v.x + v.y*v.y + v.z*v.z + v.w*v.w;
    float2 r0 = block_reduce2(s, ss);
    float mean = r0.x * (1.f / DM);
    float var = r0.y * (1.f / DM) - mean * mean;
    float rs = rsqrtf(var + 1e-5f);
    int c = t * 4;
    float o0 = (v.x - mean) * rs * w[c+0] + b[c+0];
    float o1 = (v.y - mean) * rs * w[c+1] + b[c+1];
    float o2 = (v.z - mean) * rs * w[c+2] + b[c+2];
    float o3 = (v.w - mean) * rs * w[c+3] + b[c+3];
    __half h0, h1, h2, h3, l0, l1, l2, l3;
    fsplit(o0, h0, l0); fsplit(o1, h1, l1); fsplit(o2, h2, l2); fsplit(o3, h3, l3);
    __half* a2 = g_a2 + (size_t)row * 2048;
    *(__half2*)(a2 + c)            = __halves2half2(h0, h1);
    *(__half2*)(a2 + c + 2)        = __halves2half2(h2, h3);
    *(__half2*)(a2 + 1024 + c)     = __halves2half2(l0, l1);
    *(__half2*)(a2 + 1024 + c + 2) = __halves2half2(l2, l3);
}

// ---------------------------------------------------------------------------
// Causal depthwise conv (k=4) + silu
// ---------------------------------------------------------------------------
__global__ void conv_silu_kernel(const float* __restrict__ cw, const float* __restrict__ cb) {
    int c = blockIdx.x * blockDim.x + threadIdx.x;
    if (c >= CONVD) return;
    int r = blockIdx.y;
    int b = r >> 11, l = r & (SEQ - 1);
    float w0 = cw[c*4+0], w1 = cw[c*4+1], w2 = cw[c*4+2], w3 = cw[c*4+3];
    const float* base = g_zx + (size_t)(b * SEQ) * DIP + DI + c;
    float acc = cb[c];
    if (l >= 3) acc = fmaf(w0, base[(size_t)(l-3) * DIP], acc);
    if (l >= 2) acc = fmaf(w1, base[(size_t)(l-2) * DIP], acc);
    if (l >= 1) acc = fmaf(w2, base[(size_t)(l-1) * DIP], acc);
    acc = fmaf(w3, base[(size_t)l * DIP], acc);
    g_xc[(size_t)r * CONVD + c] = acc / (1.f + expf(-acc));
}

__global__ void dt_kernel(const float* __restrict__ dt_bias, const float* __restrict__ A_log) {
    int i = blockIdx.x * blockDim.x + threadIdx.x;
    int r = i >> 5, hh = i & 31;
    float raw = g_zx[(size_t)r * DIP + (DI + CONVD) + hh];
    float v = raw + dt_bias[hh];
    float sp = (v > 20.f) ? v : log1pf(expf(v));
    g_dt[i] = sp;
    g_dA[i] = expf(-expf(A_log[hh]) * sp);
}

// ---------------------------------------------------------------------------
// Chunked selective scan (R12-proven)
// ---------------------------------------------------------------------------
__global__ __launch_bounds__(512, 1)
void scan_ph1(const float* __restrict__ Dp) {
    int t = blockIdx.x;
    int c = t & (NCH - 1);
    int bh = t >> 4;
    int b = bh >> 5, h = bh & 31;
    int tid = threadIdx.x;
    int p = tid >> 3, sub = tid & 7, n0 = sub << 3;
    int l0 = c * CHL;

    __shared__ __align__(16) float sx[2][64];
    __shared__ __align__(16) float sB[2][64];
    __shared__ __align__(16) float sC[2][64];
    __shared__ float sdt[2][2];

    float hs[8];
#pragma unroll
    for (int i = 0; i < 8; i++) hs[i] = 0.f;
    float Dv = Dp[h];
    float cp = 1.f;

    const float* xcb = g_xc + (size_t)(b * SEQ) * CONVD;
    float* yb = g_ydp + (size_t)(b * SEQ) * DI;

    for (int ll = 0; ll < CHL; ll++) {
        int l = l0 + ll;
        int buf = ll & 1;
        const float* xr = xcb + (size_t)l * CONVD;
        int ri = (b * SEQ + l) * NH + h;
        if (tid < 64)        sx[buf][tid]       = xr[h * 64 + tid];
        else if (tid < 128)  sB[buf][tid - 64]  = xr[2048 + (tid - 64)];
        else if (tid < 192)  sC[buf][tid - 128] = xr[2112 + (tid - 128)];
        else if (tid == 192) {
            sdt[buf][0] = g_dt[ri];
            sdt[buf][1] = g_dA[ri];
        }
        __syncthreads();

        float dtv = sdt[buf][0], dAv = sdt[buf][1];
        cp *= dAv;
        if (tid == 0) g_cp[ri] = cp;
        float xv = sx[buf][p];
        float dtx = dtv * xv;
        float4 Bv0 = *(const float4*)&sB[buf][n0];
        float4 Bv1 = *(const float4*)&sB[buf][n0 + 4];
        float4 Cv0 = *(const float4*)&sC[buf][n0];
        float4 Cv1 = *(const float4*)&sC[buf][n0 + 4];

        float part;
        hs[0] = fmaf(hs[0], dAv, dtx * Bv0.x); part  = hs[0] * Cv0.x;
        hs[1] = fmaf(hs[1], dAv, dtx * Bv0.y); part += hs[1] * Cv0.y;
        hs[2] = fmaf(hs[2], dAv, dtx * Bv0.z); part += hs[2] * Cv0.z;
        hs[3] = fmaf(hs[3], dAv, dtx * Bv0.w); part += hs[3] * Cv0.w;
        hs[4] = fmaf(hs[4], dAv, dtx * Bv1.x); part += hs[4] * Cv1.x;
        hs[5] = fmaf(hs[5], dAv, dtx * Bv1.y); part += hs[5] * Cv1.y;
        hs[6] = fmaf(hs[6], dAv, dtx * Bv1.z); part += hs[6] * Cv1.z;
        hs[7] = fmaf(hs[7], dAv, dtx * Bv1.w); part += hs[7] * Cv1.w;

        part += __shfl_xor_sync(0xffffffffu, part, 1);
        part += __shfl_xor_sync(0xffffffffu, part, 2);
        part += __shfl_xor_sync(0xffffffffu, part, 4);

        if (sub == 0)
            yb[(size_t)l * DI + h * 64 + p] = fmaf(Dv, xv, part);
    }

    float* Sp = g_S + (size_t)t * 4096 + p * 64 + n0;
    *(float4*)(Sp + 0) = make_float4(hs[0], hs[1], hs[2], hs[3]);
    *(float4*)(Sp + 4) = make_float4(hs[4], hs[5], hs[6], hs[7]);
}

__global__ __launch_bounds__(512, 1)
void scan_ph2() {
    int bh = blockIdx.x;
    int b = bh >> 5, h = bh & 31;
    int e = threadIdx.x * 8;
    float H[8];
#pragma unroll
    for (int i = 0; i < 8; i++) H[i] = 0.f;

    for (int c = 0; c < NCH; c++) {
        size_t t = (size_t)(bh * NCH + c);
        float* dst = g_Hin + t * 4096 + e;
        *(float4*)(dst + 0) = make_float4(H[0], H[1], H[2], H[3]);
        *(float4*)(dst + 4) = make_float4(H[4], H[5], H[6], H[7]);
        float cpT = g_cp[(b * SEQ + c * CHL + CHL - 1) * NH + h];
        const float* Sp = g_S + t * 4096 + e;
        float4 s0 = *(const float4*)(Sp + 0);
        float4 s1 = *(const float4*)(Sp + 4);
        H[0] = fmaf(cpT, H[0], s0.x); H[1] = fmaf(cpT, H[1], s0.y);
        H[2] = fmaf(cpT, H[2], s0.z); H[3] = fmaf(cpT, H[3], s0.w);
        H[4] = fmaf(cpT, H[4], s1.x); H[5] = fmaf(cpT, H[5], s1.y);
        H[6] = fmaf(cpT, H[6], s1.z); H[7] = fmaf(cpT, H[7], s1.w);
    }
}

__global__ __launch_bounds__(512, 1)
void scan_ph3() {
    int t = blockIdx.x;
    int c = t & (NCH - 1);
    int bh = t >> 4;
    int b = bh >> 5, h = bh & 31;
    int tid = threadIdx.x;
    int p = tid >> 3, sub = tid & 7, n0 = sub << 3;
    int l0 = c * CHL;

    __shared__ __align__(16) float sH[4096];
    {
        const float* src = g_Hin + (size_t)t * 4096 + tid * 8;
        float4 a = *(const float4*)(src + 0);
        float4 bb = *(const float4*)(src + 4);
        *(float4*)&sH[tid * 8 + 0] = a;
        *(float4*)&sH[tid * 8 + 4] = bb;
    }
    __syncthreads();

    float H[8];
#pragma unroll
    for (int i = 0; i < 8; i++) H[i] = sH[p * 64 + n0 + i];

    const float* xcb = g_xc + (size_t)(b * SEQ) * CONVD;
    float* yb = g_ydp + (size_t)(b * SEQ) * DI;

    for (int ll = 0; ll < CHL; ll++) {
        int l = l0 + ll;
        const float* xr = xcb + (size_t)l * CONVD;
        float cp = g_cp[(b * SEQ + l) * NH + h];
        float4 Cv0 = *(const float4*)(xr + 2112 + n0);
        float4 Cv1 = *(const float4*)(xr + 2112 + n0 + 4);
        float part = H[0] * Cv0.x + H[1] * Cv0.y + H[2] * Cv0.z + H[3] * Cv0.w
                   + H[4] * Cv1.x + H[5] * Cv1.y + H[6] * Cv1.z + H[7] * Cv1.w;
        part += __shfl_xor_sync(0xffffffffu, part, 1);
        part += __shfl_xor_sync(0xffffffffu, part, 2);
        part += __shfl_xor_sync(0xffffffffu, part, 4);
        if (sub == 0) {
            size_t yi = (size_t)l * DI + h * 64 + p;
            yb[yi] += cp * part;
        }
    }
}

// ---------------------------------------------------------------------------
// Gate + RMSNorm; writes yn fp16 split (stride 4096)
// ---------------------------------------------------------------------------
__global__ void gate_rms_kernel(const float* __restrict__ norm_w) {
    int row = blockIdx.x, t = threadIdx.x;
    const float* zr = g_zx + (size_t)row * DIP;
    const float* yr = g_ydp + (size_t)row * DI;
    int c0 = t * 8;
    float g[8];
    float ss = 0.f;
#pragma unroll
    for (int k = 0; k < 2; k++) {
        float4 zv = *(const float4*)(zr + c0 + k * 4);
        float4 yv = *(const float4*)(yr + c0 + k * 4);
        float g0 = yv.x * (zv.x / (1.f + expf(-zv.x)));
        float g1 = yv.y * (zv.y / (1.f + expf(-zv.y)));
        float g2 = yv.z * (zv.z / (1.f + expf(-zv.z)));
        float g3 = yv.w * (zv.w / (1.f + expf(-zv.w)));
        g[k*4+0] = g0; g[k*4+1] = g1; g[k*4+2] = g2; g[k*4+3] = g3;
        ss += g0*g0 + g1*g1 + g2*g2 + g3*g3;
    }
    float2 r = block_reduce2(ss, 0.f);
    float rs = rsqrtf(r.x * (1.f / DI) + 1e-5f);
    __half* a2 = g_a2 + (size_t)row * 4096;
#pragma unroll
    for (int k = 0; k < 2; k++) {
        float o0 = g[k*4+0] * rs * norm_w[c0 + k*4+0];
        float o1 = g[k*4+1] * rs * norm_w[c0 + k*4+1];
        float o2 = g[k*4+2] * rs * norm_w[c0 + k*4+2];
        float o3 = g[k*4+3] * rs * norm_w[c0 + k*4+3];
        __half h0, h1, h2, h3, l0, l1, l2, l3;
        fsplit(o0, h0, l0); fsplit(o1, h1, l1); fsplit(o2, h2, l2); fsplit(o3, h3, l3);
        int c = c0 + k * 4;
        *(__half2*)(a2 + c)            = __halves2half2(h0, h1);
        *(__half2*)(a2 + c + 2)        = __halves2half2(h2, h3);
        *(__half2*)(a2 + 2048 + c)     = __halves2half2(l0, l1);
        *(__half2*)(a2 + 2048 + c + 2) = __halves2half2(l2, l3);
    }
}

// ---------------------------------------------------------------------------
// Host launcher
// ---------------------------------------------------------------------------
extern "C" void kernel_launch(void* const* d_in, const int* in_sizes, int n_in,
                              void* d_out, int out_size) {
    const float* x         = (const float*)d_in[0];
    const float* ln0_w     = (const float*)d_in[1];
    const float* ln0_b     = (const float*)d_in[2];
    const float* ln1_w     = (const float*)d_in[3];
    const float* ln1_b     = (const float*)d_in[4];
    const float* ln2_w     = (const float*)d_in[5];
    const float* ln2_b     = (const float*)d_in[6];
    const float* in_proj_w = (const float*)d_in[7];
    const float* conv_w    = (const float*)d_in[8];
    const float* conv_b    = (const float*)d_in[9];
    const float* dt_bias   = (const float*)d_in[10];
    const float* A_log     = (const float*)d_in[11];
    const float* D_param   = (const float*)d_in[12];
    const float* norm_w    = (const float*)d_in[13];
    const float* out_proj_w= (const float*)d_in[14];
    const float* ffn_w1    = (const float*)d_in[15];
    const float* ffn_b1    = (const float*)d_in[16];
    const float* ffn_w2    = (const float*)d_in[17];
    const float* ffn_b2    = (const float*)d_in[18];
    float* out = (float*)d_out;

    float *px0, *pzx, *px1;
    __half *pa2, *pb2;
    cudaGetSymbolAddress((void**)&px0,  g_x0);
    cudaGetSymbolAddress((void**)&pzx,  g_zx);
    cudaGetSymbolAddress((void**)&px1,  g_x1);
    cudaGetSymbolAddress((void**)&pa2,  g_a2);
    cudaGetSymbolAddress((void**)&pb2,  g_b2);
    __half* pge = pa2 + (size_t)MROWS * 4096;   // gelu split region

    cudaFuncSetAttribute(gemm_mma<0>, cudaFuncAttributeMaxDynamicSharedMemorySize, GSMEM);
    cudaFuncSetAttribute(gemm_mma<1>, cudaFuncAttributeMaxDynamicSharedMemorySize, GSMEM);
    cudaFuncSetAttribute(gemm_mma<2>, cudaFuncAttributeMaxDynamicSharedMemorySize, GSMEM);
    cudaFuncSetAttribute(gemm_mma<3>, cudaFuncAttributeMaxDynamicSharedMemorySize, GSMEM);

    // 1. LN0 + LN1 (emits u split, Kp=2048)
    ln01_kernel<<<MROWS, 256>>>(x, ln0_w, ln0_b, ln1_w, ln1_b);

    // 2. in_proj: Npad=4352, Kp=2048
    cvt_wt<<<(4352 * DM) / 1024, 256>>>(in_proj_w, pb2, DIP, DM);
    gemm_mma<0><<<dim3(4352 / BN, MROWS / BM), 256, GSMEM>>>(
        pa2, pb2, pzx, nullptr, nullptr, nullptr, DIP, 2 * DM);

    // 3-6. conv, dt, chunked scan, gate (gate emits yn split, Kp=4096)
    conv_silu_kernel<<<dim3((CONVD + 255) / 256, MROWS), 256>>>(conv_w, conv_b);
    dt_kernel<<<(MROWS * NH) / 256, 256>>>(dt_bias, A_log);
    scan_ph1<<<NTASK, 512>>>(D_param);
    scan_ph2<<<B_SZ * NH, 512>>>();
    scan_ph3<<<NTASK, 512>>>();
    gate_rms_kernel<<<MROWS, 256>>>(norm_w);

    // 7. out_proj + residual(x0) -> x1  (Kp=4096)
    cvt_wt<<<(1024 * DI) / 1024, 256>>>(out_proj_w, pb2, DM, DI);
    gemm_mma<3><<<dim3(DM / BN, MROWS / BM), 256, GSMEM>>>(
        pa2, pb2, px1, nullptr, px0, nullptr, DM, 2 * DI);

    // 8. LN2 (emits hln split, Kp=2048)
    ln2_kernel<<<MROWS, 256>>>(ln2_w, ln2_b);

    // 9. FFN1 + bias + gelu -> fp16 split into gelu region (Kp=2048)
    cvt_wt<<<(FFN * DM) / 1024, 256>>>(ffn_w1, pb2, FFN, DM);
    gemm_mma<1><<<dim3(FFN / BN, MROWS / BM), 256, GSMEM>>>(
        pa2, pb2, nullptr, ffn_b1, nullptr, pge, FFN, 2 * DM);

    // 10. FFN2 + bias + residual(x1) -> out  (Kp=8192)
    cvt_wt<<<(1024 * FFN) / 1024, 256>>>(ffn_w2, pb2, DM, FFN);
    gemm_mma<2><<<dim3(DM / BN, MROWS / BM), 256, GSMEM>>>(
        pge, pb2, out, ffn_b2, px1, nullptr, DM, 2 * FFN);
}